// round 8
// baseline (speedup 1.0000x reference)
#include <cuda_runtime.h>
#include <cuda_bf16.h>
#include <stdint.h>
#include <math.h>

#define HW 16384

// ---------------- helpers ----------------
__device__ __forceinline__ uint32_t smem_u32(const void* p) {
    uint32_t a;
    asm("{ .reg .u64 t; cvta.to.shared.u64 t, %1; cvt.u32.u64 %0, t; }" : "=r"(a) : "l"(p));
    return a;
}
__device__ __forceinline__ void cp_async16(uint32_t dst, const void* src) {
    asm volatile("cp.async.cg.shared.global [%0], [%1], 16;" :: "r"(dst), "l"(src));
}
#define CP_COMMIT() asm volatile("cp.async.commit_group;" ::: "memory")
#define CP_WAIT0()  asm volatile("cp.async.wait_group 0;" ::: "memory")
#define CP_WAIT1()  asm volatile("cp.async.wait_group 1;" ::: "memory")

__device__ __forceinline__ uint32_t bf16x2_pack(float lo, float hi) {
    uint32_t r;
    asm("cvt.rn.bf16x2.f32 %0, %1, %2;" : "=r"(r) : "f"(hi), "f"(lo));
    return r;
}
__device__ __forceinline__ void ldmatrix_x4_trans(uint32_t* r, uint32_t addr) {
    asm volatile("ldmatrix.sync.aligned.m8n8.x4.trans.shared.b16 {%0,%1,%2,%3}, [%4];"
                 : "=r"(r[0]), "=r"(r[1]), "=r"(r[2]), "=r"(r[3]) : "r"(addr));
}
__device__ __forceinline__ void mma_bf16(float* d, const uint32_t* a, uint32_t b0, uint32_t b1) {
    asm("mma.sync.aligned.m16n8k16.row.col.f32.bf16.bf16.f32 "
        "{%0,%1,%2,%3},{%4,%5,%6,%7},{%8,%9},{%0,%1,%2,%3};"
        : "+f"(d[0]), "+f"(d[1]), "+f"(d[2]), "+f"(d[3])
        : "r"(a[0]), "r"(a[1]), "r"(a[2]), "r"(a[3]), "r"(b0), "r"(b1));
}

// ---------------- scratch (float units) ----------------
#define OFF_XS     0ULL           // bf16 [2,192,HW]
#define OFF_T1     3145728ULL     // bf16 [2,192,HW]
#define OFF_Q      6291456ULL     // bf16 [2,192,HW]
#define OFF_KVP    9437184ULL     // bf16 [2,384,HW]
#define OFF_KVB    15728640ULL    // bf16 [2,384,HW]
#define OFF_YP     22020096ULL    // bf16 [2,768,HW]
#define OFF_M1     34603008ULL
#define OFF_MF     34603392ULL
#define OFF_RQ     34603776ULL    // [384][8] ss partials
#define OFF_RK     34606848ULL    // [384][8]
#define OFF_SP     34609920ULL    // fp32 [2,6,8,32,32]
#define OFF_ATT    34708224ULL    // fp32 [2,6,32,32]
#define OFF_WQ     34720512ULL    // u32 13824
#define OFF_WKV    34734336ULL    // u32 9216
#define OFF_WPO    34743552ULL    // u32 18432
#define OFF_WPIN   34761984ULL    // u32 73728
#define OFF_WPOUT  34835712ULL    // u32 36864
#define SCRATCH_TOTAL 34872576ULL
__device__ float g_scratch[SCRATCH_TOTAL];

// ---------------- prep: per-batch channel multipliers + k_v tail --------------------
__global__ void prep_kernel(const float* __restrict__ kv, const float* __restrict__ wkR,
                            const float* __restrict__ wkI, const float* __restrict__ wffk,
                            float* __restrict__ m1, float* __restrict__ mf,
                            float* __restrict__ out_tail, int tail) {
    int t = blockIdx.x * blockDim.x + threadIdx.x;
    if (t < 384) {
        int b = t / 192, c = t % 192;
        float acc = 1.0f;
        if (c < 144) {
            const float* w = wkR + c * 192; const float* v = kv + b * 256;
            for (int i = 0; i < 192; i++) acc += w[i] * v[i];
        } else {
            const float* w = wkI + (c - 144) * 64; const float* v = kv + b * 256 + 192;
            for (int i = 0; i < 64; i++) acc += w[i] * v[i];
        }
        m1[t] = acc;
    } else if (t < 768) {
        int u = t - 384; int b = u / 192, c = u % 192;
        float acc = 1.0f;
        const float* w = wffk + c * 256; const float* v = kv + b * 256;
        for (int i = 0; i < 256; i++) acc += w[i] * v[i];
        mf[u] = acc;
    } else if (t - 768 < tail) {
        out_tail[t - 768] = kv[t - 768];
    }
}

// ------- pack weights W[oc][ic] into bf16 A-fragment order (u32 = bf16x2) -----------
__device__ __forceinline__ void pack_one(const float* __restrict__ W, int ic, int NKC,
                                         uint32_t* __restrict__ pack, int idx) {
    int reg = idx & 3, lane = (idx >> 2) & 31, mi = (idx >> 7) & 3;
    int kc = (idx >> 9) % NKC, ocb = (idx >> 9) / NKC;
    int g = lane >> 2, tig = lane & 3;
    int oc = ocb * 64 + mi * 16 + g + (reg & 1) * 8;
    int k = kc * 16 + tig * 2 + (reg >> 1) * 8;
    pack[idx] = bf16x2_pack(W[(size_t)oc * ic + k], W[(size_t)oc * ic + k + 1]);
}

__global__ void wpack_all_kernel(const float* __restrict__ wq, const float* __restrict__ wkv,
                                 const float* __restrict__ wpo, const float* __restrict__ wpin,
                                 const float* __restrict__ wpout,
                                 uint32_t* __restrict__ pq, uint32_t* __restrict__ pkv,
                                 uint32_t* __restrict__ ppo, uint32_t* __restrict__ ppin,
                                 uint32_t* __restrict__ ppout) {
    int idx = blockIdx.x * 256 + threadIdx.x;
    if (idx < 13824)        pack_one(wq,    144,  9, pq,    idx);
    else if (idx < 23040)   pack_one(wkv,    48,  3, pkv,   idx - 13824);
    else if (idx < 41472)   pack_one(wpo,   192, 12, ppo,   idx - 23040);
    else if (idx < 115200)  pack_one(wpin,  192, 12, ppin,  idx - 41472);
    else if (idx < 152064)  pack_one(wpout, 384, 24, ppout, idx - 115200);
}

// ------- channel LayerNorm * per-(b,c) multiplier -> bf16 --------------------------
__global__ void ln_scale_kernel(const float* __restrict__ x, const float* __restrict__ w,
                                const float* __restrict__ bias, const float* __restrict__ m,
                                __nv_bfloat16* __restrict__ out) {
    int p = blockIdx.x * blockDim.x + threadIdx.x;
    int b = p >> 14, px = p & (HW - 1);
    const float* xb = x + (size_t)b * 192 * HW + px;
    float s = 0.f, s2 = 0.f;
    #pragma unroll 8
    for (int c = 0; c < 192; c++) { float v = xb[(size_t)c * HW]; s += v; s2 += v * v; }
    float mu = s * (1.0f / 192.0f);
    float rstd = rsqrtf(s2 * (1.0f / 192.0f) - mu * mu + 1e-5f);
    __nv_bfloat16* ob = out + (size_t)b * 192 * HW + px;
    const float* mb = m + b * 192;
    #pragma unroll 8
    for (int c = 0; c < 192; c++) {
        float v = (xb[(size_t)c * HW] - mu) * rstd * w[c] + bias[c];
        ob[(size_t)c * HW] = __float2bfloat16(v * mb[c]);
    }
}

// ------- bf16 mma.sync conv1x1, warp-autonomous (unchanged from R7) ------------------
__global__ void __launch_bounds__(256) conv_mma_kernel(
        const __nv_bfloat16* __restrict__ in, int ictot, int icoff, int NKC,
        const uint32_t* __restrict__ wpack, int octot, int tpc,
        const float* __restrict__ res, float* __restrict__ outf,
        __nv_bfloat16* __restrict__ outb) {
    extern __shared__ char sm[];
    char* sIn = sm + NKC * 2048;
    int tid = threadIdx.x, wid = tid >> 5, lane = tid & 31;
    int g = lane >> 2, tig = lane & 3;
    int ocbase = blockIdx.y * 64;

    {
        const uint4* gw = (const uint4*)(wpack + (size_t)blockIdx.y * NKC * 512);
        uint4* sw4 = (uint4*)sm;
        for (int i = tid; i < NKC * 128; i += 256) sw4[i] = gw[i];
    }
    __syncthreads();

    uint32_t wInb = smem_u32(sIn) + (uint32_t)wid * 2048u;
    int lm = lane >> 3, lr = lane & 7;
    uint32_t lmrow = (uint32_t)(((lm & 1) * 8 + lr) * 64 + (lm >> 1) * 16);

    for (int t = 0; t < tpc; t++) {
        int pxg = (blockIdx.x * tpc + t) * 256;
        int b = pxg >> 14, pxb = pxg & (HW - 1);
        const __nv_bfloat16* gin = in + ((size_t)b * ictot + icoff) * HW + pxb + wid * 32;

        #pragma unroll
        for (int i = 0; i < 2; i++) {
            int u = lane + 32 * i;
            int r = u >> 2, c = u & 3;
            cp_async16(wInb + (uint32_t)(r * 64 + c * 16), gin + (size_t)r * HW + c * 8);
        }
        CP_COMMIT();

        float d[4][4][4];
        #pragma unroll
        for (int mi = 0; mi < 4; mi++)
            #pragma unroll
            for (int ni = 0; ni < 4; ni++)
                #pragma unroll
                for (int r = 0; r < 4; r++) d[mi][ni][r] = 0.f;

        for (int kc = 0; kc < NKC; kc++) {
            if (kc + 1 < NKC) {
                const __nv_bfloat16* src = gin + (size_t)(kc + 1) * 16 * HW;
                uint32_t dstb = wInb + (uint32_t)((kc + 1) & 1) * 1024u;
                #pragma unroll
                for (int i = 0; i < 2; i++) {
                    int u = lane + 32 * i;
                    int r = u >> 2, c = u & 3;
                    cp_async16(dstb + (uint32_t)(r * 64 + c * 16), src + (size_t)r * HW + c * 8);
                }
                CP_COMMIT();
                CP_WAIT1();
            } else {
                CP_WAIT0();
            }
            __syncwarp();

            uint32_t bufb = wInb + (uint32_t)(kc & 1) * 1024u;
            uint32_t bfr[2][4];
            ldmatrix_x4_trans(bfr[0], bufb + lmrow);
            ldmatrix_x4_trans(bfr[1], bufb + lmrow + 32);

            const uint4* wk = (const uint4*)(sm + kc * 2048);
            #pragma unroll
            for (int mi = 0; mi < 4; mi++) {
                uint4 av4 = wk[mi * 32 + lane];
                uint32_t a[4] = {av4.x, av4.y, av4.z, av4.w};
                mma_bf16(d[mi][0], a, bfr[0][0], bfr[0][1]);
                mma_bf16(d[mi][1], a, bfr[0][2], bfr[0][3]);
                mma_bf16(d[mi][2], a, bfr[1][0], bfr[1][1]);
                mma_bf16(d[mi][3], a, bfr[1][2], bfr[1][3]);
            }
        }

        #pragma unroll
        for (int mi = 0; mi < 4; mi++) {
            int oc0 = ocbase + mi * 16 + g;
            #pragma unroll
            for (int ni = 0; ni < 4; ni++) {
                int px0 = pxb + wid * 32 + ni * 8 + tig * 2;
                size_t o0 = ((size_t)b * octot + oc0) * HW + px0;
                size_t o2 = o0 + (size_t)8 * HW;
                float v0 = d[mi][ni][0], v1 = d[mi][ni][1];
                float v2 = d[mi][ni][2], v3 = d[mi][ni][3];
                if (outf) {
                    if (res) {
                        float2 e0 = *(const float2*)(res + o0);
                        float2 e2 = *(const float2*)(res + o2);
                        v0 += e0.x; v1 += e0.y; v2 += e2.x; v3 += e2.y;
                    }
                    *(float2*)(outf + o0) = make_float2(v0, v1);
                    *(float2*)(outf + o2) = make_float2(v2, v3);
                } else {
                    *(uint32_t*)(outb + o0) = bf16x2_pack(v0, v1);
                    *(uint32_t*)(outb + o2) = bf16x2_pack(v2, v3);
                }
            }
        }
    }
}

// ------- vectorized depthwise 3x3 (8 px/thread) + optional ss partials ---------------
// block = (plane, 16-row segment); 256 threads x 8 px = 2048 px
__global__ void __launch_bounds__(256) dwconv_v_kernel(
        const __nv_bfloat16* __restrict__ in, const float* __restrict__ w, int C,
        __nv_bfloat16* __restrict__ out, int ssC, float* __restrict__ ss) {
    int blk = blockIdx.x;
    int seg = blk & 7, plane = blk >> 3;
    int c = plane % C, b = plane / C;
    const __nv_bfloat16* ip = in + (size_t)plane * HW;
    const float* wp = w + c * 9;
    float wr[9];
    #pragma unroll
    for (int i = 0; i < 9; i++) wr[i] = wp[i];

    int tid = threadIdx.x;
    int p = tid * 8;
    int ly = p >> 7, x0 = p & 127;
    int y = seg * 16 + ly;

    float row[3][10];
    #pragma unroll
    for (int ky = 0; ky < 3; ky++) {
        int yy = y + ky - 1;
        if (yy >= 0 && yy <= 127) {
            const __nv_bfloat16* rp = ip + yy * 128;
            row[ky][0] = (x0 > 0) ? __bfloat162float(rp[x0 - 1]) : 0.f;
            uint4 m = *(const uint4*)(rp + x0);
            const __nv_bfloat16* mb = (const __nv_bfloat16*)&m;
            #pragma unroll
            for (int j = 0; j < 8; j++) row[ky][1 + j] = __bfloat162float(mb[j]);
            row[ky][9] = (x0 < 120) ? __bfloat162float(rp[x0 + 8]) : 0.f;
        } else {
            #pragma unroll
            for (int j = 0; j < 10; j++) row[ky][j] = 0.f;
        }
    }

    float ssl = 0.f;
    uint32_t pk[4];
    #pragma unroll
    for (int j = 0; j < 4; j++) {
        float a0 = 0.f, a1 = 0.f;
        #pragma unroll
        for (int ky = 0; ky < 3; ky++)
            #pragma unroll
            for (int kx = 0; kx < 3; kx++) {
                a0 += row[ky][2 * j + kx] * wr[ky * 3 + kx];
                a1 += row[ky][2 * j + 1 + kx] * wr[ky * 3 + kx];
            }
        ssl += a0 * a0 + a1 * a1;
        pk[j] = bf16x2_pack(a0, a1);
    }
    *(uint4*)(out + (size_t)plane * HW + y * 128 + x0) = *(uint4*)pk;

    if (c < ssC) {   // deterministic per-segment ss partial
        __shared__ float red[8];
        #pragma unroll
        for (int o = 16; o; o >>= 1) ssl += __shfl_down_sync(0xffffffffu, ssl, o);
        if ((tid & 31) == 0) red[tid >> 5] = ssl;
        __syncthreads();
        if (tid == 0) {
            float s = 0.f;
            #pragma unroll
            for (int i = 0; i < 8; i++) s += red[i];
            ss[(b * 192 + c) * 8 + seg] = s;
        }
    }
}

// ------- vectorized fused depthwise 3x3 (768ch pair) + gelu gate ---------------------
__global__ void __launch_bounds__(256) dwconv_gelu_v_kernel(
        const __nv_bfloat16* __restrict__ in, const float* __restrict__ w,
        __nv_bfloat16* __restrict__ out) {
    int blk = blockIdx.x;
    int seg = blk & 7, pl = blk >> 3;         // pl = b*384 + c
    int c = pl % 384, b = pl / 384;
    const __nv_bfloat16* ip1 = in + ((size_t)b * 768 + c) * HW;
    const __nv_bfloat16* ip2 = ip1 + (size_t)384 * HW;
    const float* w1p = w + c * 9;
    const float* w2p = w + (c + 384) * 9;
    float w1[9], w2[9];
    #pragma unroll
    for (int i = 0; i < 9; i++) { w1[i] = w1p[i]; w2[i] = w2p[i]; }

    int tid = threadIdx.x;
    int p = tid * 8;
    int ly = p >> 7, x0 = p & 127;
    int y = seg * 16 + ly;

    float r1[3][10], r2[3][10];
    #pragma unroll
    for (int ky = 0; ky < 3; ky++) {
        int yy = y + ky - 1;
        if (yy >= 0 && yy <= 127) {
            const __nv_bfloat16* a = ip1 + yy * 128;
            const __nv_bfloat16* bb = ip2 + yy * 128;
            r1[ky][0] = (x0 > 0) ? __bfloat162float(a[x0 - 1]) : 0.f;
            r2[ky][0] = (x0 > 0) ? __bfloat162float(bb[x0 - 1]) : 0.f;
            uint4 m1v = *(const uint4*)(a + x0);
            uint4 m2v = *(const uint4*)(bb + x0);
            const __nv_bfloat16* m1b = (const __nv_bfloat16*)&m1v;
            const __nv_bfloat16* m2b = (const __nv_bfloat16*)&m2v;
            #pragma unroll
            for (int j = 0; j < 8; j++) {
                r1[ky][1 + j] = __bfloat162float(m1b[j]);
                r2[ky][1 + j] = __bfloat162float(m2b[j]);
            }
            r1[ky][9] = (x0 < 120) ? __bfloat162float(a[x0 + 8]) : 0.f;
            r2[ky][9] = (x0 < 120) ? __bfloat162float(bb[x0 + 8]) : 0.f;
        } else {
            #pragma unroll
            for (int j = 0; j < 10; j++) { r1[ky][j] = 0.f; r2[ky][j] = 0.f; }
        }
    }

    uint32_t pk[4];
    #pragma unroll
    for (int j = 0; j < 4; j++) {
        float v[2];
        #pragma unroll
        for (int h = 0; h < 2; h++) {
            float a1 = 0.f, a2 = 0.f;
            #pragma unroll
            for (int ky = 0; ky < 3; ky++)
                #pragma unroll
                for (int kx = 0; kx < 3; kx++) {
                    a1 += r1[ky][2 * j + h + kx] * w1[ky * 3 + kx];
                    a2 += r2[ky][2 * j + h + kx] * w2[ky * 3 + kx];
                }
            float ge = 0.5f * a1 * (1.0f + erff(a1 * 0.70710678118654752f));
            v[h] = ge * a2;
        }
        pk[j] = bf16x2_pack(v[0], v[1]);
    }
    *(uint4*)(out + (size_t)pl * HW + y * 128 + x0) = *(uint4*)pk;
}

// ---------------- q@k^T partials, bf16 in -------------------------------------------
__global__ void qk_kernel(const __nv_bfloat16* __restrict__ q,
                          const __nv_bfloat16* __restrict__ kv,
                          float* __restrict__ Sp) {
    int pc = blockIdx.x, hh = blockIdx.y, b = blockIdx.z;
    const __nv_bfloat16* qb = q  + ((size_t)b * 192 + hh * 32) * HW + pc * 2048;
    const __nv_bfloat16* kb = kv + ((size_t)b * 384 + hh * 32) * HW + pc * 2048;
    __shared__ float sq[32 * 33];
    __shared__ float sk[32 * 33];
    int t = threadIdx.x;
    int i = t & 31, jg = t >> 5;
    float acc[4] = {0.f, 0.f, 0.f, 0.f};
    for (int p0 = 0; p0 < 2048; p0 += 32) {
        #pragma unroll
        for (int l = 0; l < 4; l++) {
            int idx = t + l * 256;
            int r = idx >> 5, cc = idx & 31;
            sq[r * 33 + cc] = __bfloat162float(qb[(size_t)r * HW + p0 + cc]);
            sk[r * 33 + cc] = __bfloat162float(kb[(size_t)r * HW + p0 + cc]);
        }
        __syncthreads();
        #pragma unroll
        for (int p = 0; p < 32; p++) {
            float a = sq[i * 33 + p];
            #pragma unroll
            for (int j = 0; j < 4; j++) acc[j] += a * sk[(jg * 4 + j) * 33 + p];
        }
        __syncthreads();
    }
    float* sp = Sp + (((size_t)(b * 6 + hh) * 8 + pc) * 1024);
    #pragma unroll
    for (int j = 0; j < 4; j++) sp[i * 32 + jg * 4 + j] = acc[j];
}

// ---------------- softmax (sums ss partials, applies rsqrt norms) --------------------
__global__ void softmax_kernel(const float* __restrict__ Sp, const float* __restrict__ rqp,
                               const float* __restrict__ rkp, const float* __restrict__ temp,
                               float* __restrict__ attn) {
    int bh = blockIdx.x;
    int b = bh / 6, hh = bh % 6;
    int t = threadIdx.x;
    int i = t >> 5, j = t & 31;
    const float* sp = Sp + (size_t)bh * 8192 + i * 32 + j;
    float s = 0.f;
    #pragma unroll
    for (int pc = 0; pc < 8; pc++) s += sp[pc * 1024];
    float sq = 0.f, sk = 0.f;
    const float* rq8 = rqp + (b * 192 + hh * 32 + i) * 8;
    const float* rk8 = rkp + (b * 192 + hh * 32 + j) * 8;
    #pragma unroll
    for (int k = 0; k < 8; k++) { sq += rq8[k]; sk += rk8[k]; }
    float rqv = 1.0f / fmaxf(sqrtf(sq), 1e-12f);
    float rkv = 1.0f / fmaxf(sqrtf(sk), 1e-12f);
    s *= rqv * rkv * temp[hh];
    float mx = s;
    #pragma unroll
    for (int o = 16; o; o >>= 1) mx = fmaxf(mx, __shfl_xor_sync(0xffffffffu, mx, o));
    float e = expf(s - mx);
    float sum = e;
    #pragma unroll
    for (int o = 16; o; o >>= 1) sum += __shfl_xor_sync(0xffffffffu, sum, o);
    attn[(size_t)bh * 1024 + i * 32 + j] = e / sum;
}

// ---------------- out = attn @ v, bf16 ----------------------------------------------
__global__ void av_kernel(const float* __restrict__ attn,
                          const __nv_bfloat16* __restrict__ kv,
                          __nv_bfloat16* __restrict__ out) {
    int b = blockIdx.z, hh = blockIdx.y;
    int p = blockIdx.x * 256 + threadIdx.x;
    __shared__ float sA[1024];
    for (int l = threadIdx.x; l < 1024; l += 256)
        sA[l] = attn[(size_t)(b * 6 + hh) * 1024 + l];
    __syncthreads();
    const __nv_bfloat16* vb = kv + ((size_t)b * 384 + 192 + hh * 32) * HW + p;
    float v[32];
    #pragma unroll
    for (int e = 0; e < 32; e++) v[e] = __bfloat162float(vb[(size_t)e * HW]);
    __nv_bfloat16* ob = out + ((size_t)b * 192 + hh * 32) * HW + p;
    #pragma unroll
    for (int i = 0; i < 32; i++) {
        float acc = 0.f;
        #pragma unroll
        for (int e = 0; e < 32; e++) acc += sA[i * 32 + e] * v[e];
        ob[(size_t)i * HW] = __float2bfloat16(acc);
    }
}

// ====================================================================================
extern "C" void kernel_launch(void* const* d_in, const int* in_sizes, int n_in,
                              void* d_out, int out_size) {
    const float* x      = (const float*)d_in[0];
    const float* k_v    = (const float*)d_in[1];
    const float* ln1_w  = (const float*)d_in[2];
    const float* ln1_b  = (const float*)d_in[3];
    const float* temp   = (const float*)d_in[4];
    const float* w_kR   = (const float*)d_in[5];
    const float* w_kI   = (const float*)d_in[6];
    const float* w_qR   = (const float*)d_in[7];
    const float* w_qdw  = (const float*)d_in[8];
    const float* w_kvI  = (const float*)d_in[9];
    const float* w_kvdw = (const float*)d_in[10];
    const float* w_po   = (const float*)d_in[11];
    const float* ln2_w  = (const float*)d_in[12];
    const float* ln2_b  = (const float*)d_in[13];
    const float* w_ffk  = (const float*)d_in[14];
    const float* w_pin  = (const float*)d_in[15];
    const float* w_dw   = (const float*)d_in[16];
    const float* w_pout = (const float*)d_in[17];
    float* out = (float*)d_out;

    float* sc = nullptr;
    cudaGetSymbolAddress((void**)&sc, g_scratch);
    __nv_bfloat16* xs  = (__nv_bfloat16*)(sc + OFF_XS);
    __nv_bfloat16* t1  = (__nv_bfloat16*)(sc + OFF_T1);
    __nv_bfloat16* q   = (__nv_bfloat16*)(sc + OFF_Q);
    __nv_bfloat16* kvp = (__nv_bfloat16*)(sc + OFF_KVP);
    __nv_bfloat16* kvb = (__nv_bfloat16*)(sc + OFF_KVB);
    __nv_bfloat16* yp  = (__nv_bfloat16*)(sc + OFF_YP);
    float* m1  = sc + OFF_M1;
    float* mf  = sc + OFF_MF;
    float* rq  = sc + OFF_RQ;
    float* rk  = sc + OFF_RK;
    float* Sp  = sc + OFF_SP;
    float* att = sc + OFF_ATT;
    uint32_t* wq    = (uint32_t*)(sc + OFF_WQ);
    uint32_t* wkv   = (uint32_t*)(sc + OFF_WKV);
    uint32_t* wpo   = (uint32_t*)(sc + OFF_WPO);
    uint32_t* wpin  = (uint32_t*)(sc + OFF_WPIN);
    uint32_t* wpout = (uint32_t*)(sc + OFF_WPOUT);

    cudaFuncSetAttribute(conv_mma_kernel, cudaFuncAttributeMaxDynamicSharedMemorySize, 66560);
    auto smb = [](int NKC) { return (size_t)NKC * 2048 + 16384; };

    int tail = out_size - 6291456;
    if (tail < 0) tail = 0;
    if (tail > 512) tail = 512;

    // launches 1-3 (launch #4 = conv_q for ncu capture)
    prep_kernel<<<5, 256>>>(k_v, w_kR, w_kI, w_ffk, m1, mf, out + 6291456, tail);
    wpack_all_kernel<<<594, 256>>>(w_qR, w_kvI, w_po, w_pin, w_pout,
                                   wq, wkv, wpo, wpin, wpout);
    ln_scale_kernel<<<128, 256>>>(x, ln1_w, ln1_b, m1, xs);

    // attention branch
    conv_mma_kernel<<<dim3(64, 3), 256, smb(9)>>>(xs, 192, 0, 9, wq, 192, 2,
                                                  nullptr, nullptr, t1);
    conv_mma_kernel<<<dim3(64, 6), 256, smb(3)>>>(xs, 192, 144, 3, wkv, 384, 2,
                                                  nullptr, nullptr, kvp);
    dwconv_v_kernel<<<2 * 192 * 8, 256>>>(t1, w_qdw, 192, q, 192, rq);
    dwconv_v_kernel<<<2 * 384 * 8, 256>>>(kvp, w_kvdw, 384, kvb, 192, rk);
    qk_kernel<<<dim3(8, 6, 2), 256>>>(q, kvb, Sp);
    softmax_kernel<<<12, 1024>>>(Sp, rq, rk, temp, att);
    av_kernel<<<dim3(64, 6, 2), 256>>>(att, kvb, t1);
    conv_mma_kernel<<<dim3(64, 3), 256, smb(12)>>>(t1, 192, 0, 12, wpo, 192, 2,
                                                   x, out, nullptr);

    // GDFN feed-forward
    ln_scale_kernel<<<128, 256>>>(out, ln2_w, ln2_b, mf, xs);
    conv_mma_kernel<<<dim3(16, 12), 256, smb(12)>>>(xs, 192, 0, 12, wpin, 768, 8,
                                                    nullptr, nullptr, yp);
    dwconv_gelu_v_kernel<<<2 * 384 * 8, 256>>>(yp, w_dw, kvp);
    conv_mma_kernel<<<dim3(64, 3), 256, smb(24)>>>(kvp, 384, 0, 24, wpout, 192, 2,
                                                   out, out, nullptr);
}

// round 9
// speedup vs baseline: 1.2226x; 1.2226x over previous
#include <cuda_runtime.h>
#include <cuda_bf16.h>
#include <stdint.h>
#include <math.h>

#define HW 16384

// ---------------- helpers ----------------
__device__ __forceinline__ uint32_t smem_u32(const void* p) {
    uint32_t a;
    asm("{ .reg .u64 t; cvta.to.shared.u64 t, %1; cvt.u32.u64 %0, t; }" : "=r"(a) : "l"(p));
    return a;
}
__device__ __forceinline__ void cp_async16(uint32_t dst, const void* src) {
    asm volatile("cp.async.cg.shared.global [%0], [%1], 16;" :: "r"(dst), "l"(src));
}
#define CP_COMMIT() asm volatile("cp.async.commit_group;" ::: "memory")
#define CP_WAIT0()  asm volatile("cp.async.wait_group 0;" ::: "memory")
#define CP_WAIT1()  asm volatile("cp.async.wait_group 1;" ::: "memory")
#define CP_WAIT2()  asm volatile("cp.async.wait_group 2;" ::: "memory")

__device__ __forceinline__ uint32_t bf16x2_pack(float lo, float hi) {
    uint32_t r;
    asm("cvt.rn.bf16x2.f32 %0, %1, %2;" : "=r"(r) : "f"(hi), "f"(lo));
    return r;
}
__device__ __forceinline__ void ldmatrix_x4_trans(uint32_t* r, uint32_t addr) {
    asm volatile("ldmatrix.sync.aligned.m8n8.x4.trans.shared.b16 {%0,%1,%2,%3}, [%4];"
                 : "=r"(r[0]), "=r"(r[1]), "=r"(r[2]), "=r"(r[3]) : "r"(addr));
}
__device__ __forceinline__ void mma_bf16(float* d, const uint32_t* a, uint32_t b0, uint32_t b1) {
    asm("mma.sync.aligned.m16n8k16.row.col.f32.bf16.bf16.f32 "
        "{%0,%1,%2,%3},{%4,%5,%6,%7},{%8,%9},{%0,%1,%2,%3};"
        : "+f"(d[0]), "+f"(d[1]), "+f"(d[2]), "+f"(d[3])
        : "r"(a[0]), "r"(a[1]), "r"(a[2]), "r"(a[3]), "r"(b0), "r"(b1));
}

// ---------------- scratch (float units) ----------------
#define OFF_XS     0ULL           // bf16 [2,192,HW]
#define OFF_T1     3145728ULL     // bf16 [2,192,HW]
#define OFF_Q      6291456ULL     // bf16 [2,192,HW]
#define OFF_KVP    9437184ULL     // bf16 [2,384,HW]
#define OFF_KVB    15728640ULL    // bf16 [2,384,HW]
#define OFF_YP     22020096ULL    // bf16 [2,768,HW]
#define OFF_M1     34603008ULL
#define OFF_MF     34603392ULL
#define OFF_RQ     34603776ULL
#define OFF_RK     34604160ULL
#define OFF_SP     34604544ULL    // fp32 [2,6,8,32,32]
#define OFF_ATT    34702848ULL    // fp32 [2,6,32,32]
#define OFF_WQ     34715136ULL    // u32 13824
#define OFF_WKV    34728960ULL    // u32 9216
#define OFF_WPO    34738176ULL    // u32 18432
#define OFF_WPIN   34756608ULL    // u32 73728
#define OFF_WPOUT  34830336ULL    // u32 36864
#define SCRATCH_TOTAL 34867200ULL
__device__ float g_scratch[SCRATCH_TOTAL];

// ---------------- prep: per-batch channel multipliers + k_v tail --------------------
__global__ void prep_kernel(const float* __restrict__ kv, const float* __restrict__ wkR,
                            const float* __restrict__ wkI, const float* __restrict__ wffk,
                            float* __restrict__ m1, float* __restrict__ mf,
                            float* __restrict__ out_tail, int tail) {
    int t = blockIdx.x * blockDim.x + threadIdx.x;
    if (t < 384) {
        int b = t / 192, c = t % 192;
        float acc = 1.0f;
        if (c < 144) {
            const float* w = wkR + c * 192; const float* v = kv + b * 256;
            for (int i = 0; i < 192; i++) acc += w[i] * v[i];
        } else {
            const float* w = wkI + (c - 144) * 64; const float* v = kv + b * 256 + 192;
            for (int i = 0; i < 64; i++) acc += w[i] * v[i];
        }
        m1[t] = acc;
    } else if (t < 768) {
        int u = t - 384; int b = u / 192, c = u % 192;
        float acc = 1.0f;
        const float* w = wffk + c * 256; const float* v = kv + b * 256;
        for (int i = 0; i < 256; i++) acc += w[i] * v[i];
        mf[u] = acc;
    } else if (t - 768 < tail) {
        out_tail[t - 768] = kv[t - 768];
    }
}

// ------- pack weights W[oc][ic] into bf16 A-fragment order (u32 = bf16x2) -----------
__device__ __forceinline__ void pack_one(const float* __restrict__ W, int ic, int NKC,
                                         uint32_t* __restrict__ pack, int idx) {
    int reg = idx & 3, lane = (idx >> 2) & 31, mi = (idx >> 7) & 3;
    int kc = (idx >> 9) % NKC, ocb = (idx >> 9) / NKC;
    int g = lane >> 2, tig = lane & 3;
    int oc = ocb * 64 + mi * 16 + g + (reg & 1) * 8;
    int k = kc * 16 + tig * 2 + (reg >> 1) * 8;
    pack[idx] = bf16x2_pack(W[(size_t)oc * ic + k], W[(size_t)oc * ic + k + 1]);
}

__global__ void wpack_all_kernel(const float* __restrict__ wq, const float* __restrict__ wkv,
                                 const float* __restrict__ wpo, const float* __restrict__ wpin,
                                 const float* __restrict__ wpout,
                                 uint32_t* __restrict__ pq, uint32_t* __restrict__ pkv,
                                 uint32_t* __restrict__ ppo, uint32_t* __restrict__ ppin,
                                 uint32_t* __restrict__ ppout) {
    int idx = blockIdx.x * 256 + threadIdx.x;
    if (idx < 13824)        pack_one(wq,    144,  9, pq,    idx);
    else if (idx < 23040)   pack_one(wkv,    48,  3, pkv,   idx - 13824);
    else if (idx < 41472)   pack_one(wpo,   192, 12, ppo,   idx - 23040);
    else if (idx < 115200)  pack_one(wpin,  192, 12, ppin,  idx - 41472);
    else if (idx < 152064)  pack_one(wpout, 384, 24, ppout, idx - 115200);
}

// ------- channel LayerNorm * per-(b,c) multiplier -> bf16 --------------------------
__global__ void ln_scale_kernel(const float* __restrict__ x, const float* __restrict__ w,
                                const float* __restrict__ bias, const float* __restrict__ m,
                                __nv_bfloat16* __restrict__ out) {
    int p = blockIdx.x * blockDim.x + threadIdx.x;
    int b = p >> 14, px = p & (HW - 1);
    const float* xb = x + (size_t)b * 192 * HW + px;
    float s = 0.f, s2 = 0.f;
    #pragma unroll 8
    for (int c = 0; c < 192; c++) { float v = xb[(size_t)c * HW]; s += v; s2 += v * v; }
    float mu = s * (1.0f / 192.0f);
    float rstd = rsqrtf(s2 * (1.0f / 192.0f) - mu * mu + 1e-5f);
    __nv_bfloat16* ob = out + (size_t)b * 192 * HW + px;
    const float* mb = m + b * 192;
    #pragma unroll 8
    for (int c = 0; c < 192; c++) {
        float v = (xb[(size_t)c * HW] - mu) * rstd * w[c] + bias[c];
        ob[(size_t)c * HW] = __float2bfloat16(v * mb[c]);
    }
}

// ------- bf16 mma.sync conv1x1, warp-autonomous, 3-stage cp.async pipeline -----------
// block 256px x 64oc; warp 32px x 64oc with 3 private 1KB input buffers
__global__ void __launch_bounds__(256) conv_mma_kernel(
        const __nv_bfloat16* __restrict__ in, int ictot, int icoff, int NKC,
        const uint32_t* __restrict__ wpack, int octot, int tpc,
        const float* __restrict__ res, float* __restrict__ outf,
        __nv_bfloat16* __restrict__ outb) {
    extern __shared__ char sm[];
    char* sIn = sm + NKC * 2048;                 // 8 warps x 3 bufs x 1KB
    int tid = threadIdx.x, wid = tid >> 5, lane = tid & 31;
    int g = lane >> 2, tig = lane & 3;
    int ocbase = blockIdx.y * 64;

    {   // resident packed A-weights for this 64-oc slice
        const uint4* gw = (const uint4*)(wpack + (size_t)blockIdx.y * NKC * 512);
        uint4* sw4 = (uint4*)sm;
        for (int i = tid; i < NKC * 128; i += 256) sw4[i] = gw[i];
    }
    __syncthreads();

    uint32_t wInb = smem_u32(sIn) + (uint32_t)wid * 3072u;
    int lm = lane >> 3, lr = lane & 7;
    uint32_t lmrow = (uint32_t)(((lm & 1) * 8 + lr) * 64 + (lm >> 1) * 16);
    int ldr = lane >> 2, ldc = lane & 3;        // cp.async source mapping

    for (int t = 0; t < tpc; t++) {
        int pxg = (blockIdx.x * tpc + t) * 256;
        int b = pxg >> 14, pxb = pxg & (HW - 1);
        const __nv_bfloat16* gin = in + ((size_t)b * ictot + icoff) * HW + pxb + wid * 32;

        // prologue: chunks 0,1 -> bufs 0,1
        #pragma unroll
        for (int pc = 0; pc < 2; pc++) {
            const __nv_bfloat16* src = gin + (size_t)pc * 16 * HW;
            uint32_t dstb = wInb + (uint32_t)pc * 1024u;
            #pragma unroll
            for (int i = 0; i < 2; i++) {
                int r = ldr + 8 * i;
                cp_async16(dstb + (uint32_t)(r * 64 + ldc * 16), src + (size_t)r * HW + ldc * 8);
            }
            CP_COMMIT();
        }

        float d[4][4][4];
        #pragma unroll
        for (int mi = 0; mi < 4; mi++)
            #pragma unroll
            for (int ni = 0; ni < 4; ni++)
                #pragma unroll
                for (int r = 0; r < 4; r++) d[mi][ni][r] = 0.f;

        for (int kc = 0; kc < NKC; kc++) {
            if (kc + 2 < NKC) {
                const __nv_bfloat16* src = gin + (size_t)(kc + 2) * 16 * HW;
                uint32_t dstb = wInb + (uint32_t)((kc + 2) % 3) * 1024u;
                #pragma unroll
                for (int i = 0; i < 2; i++) {
                    int r = ldr + 8 * i;
                    cp_async16(dstb + (uint32_t)(r * 64 + ldc * 16), src + (size_t)r * HW + ldc * 8);
                }
                CP_COMMIT();
                CP_WAIT2();
            } else if (kc == NKC - 2) {
                CP_WAIT1();
            } else {
                CP_WAIT0();
            }
            __syncwarp();

            uint32_t bufb = wInb + (uint32_t)(kc % 3) * 1024u;
            uint32_t bfr[2][4];
            ldmatrix_x4_trans(bfr[0], bufb + lmrow);
            ldmatrix_x4_trans(bfr[1], bufb + lmrow + 32);

            const uint4* wk = (const uint4*)(sm + kc * 2048);
            #pragma unroll
            for (int mi = 0; mi < 4; mi++) {
                uint4 av4 = wk[mi * 32 + lane];
                uint32_t a[4] = {av4.x, av4.y, av4.z, av4.w};
                mma_bf16(d[mi][0], a, bfr[0][0], bfr[0][1]);
                mma_bf16(d[mi][1], a, bfr[0][2], bfr[0][3]);
                mma_bf16(d[mi][2], a, bfr[1][0], bfr[1][1]);
                mma_bf16(d[mi][3], a, bfr[1][2], bfr[1][3]);
            }
        }

        #pragma unroll
        for (int mi = 0; mi < 4; mi++) {
            int oc0 = ocbase + mi * 16 + g;
            #pragma unroll
            for (int ni = 0; ni < 4; ni++) {
                int px0 = pxb + wid * 32 + ni * 8 + tig * 2;
                size_t o0 = ((size_t)b * octot + oc0) * HW + px0;
                size_t o2 = o0 + (size_t)8 * HW;
                float v0 = d[mi][ni][0], v1 = d[mi][ni][1];
                float v2 = d[mi][ni][2], v3 = d[mi][ni][3];
                if (outf) {
                    if (res) {
                        float2 e0 = *(const float2*)(res + o0);
                        float2 e2 = *(const float2*)(res + o2);
                        v0 += e0.x; v1 += e0.y; v2 += e2.x; v3 += e2.y;
                    }
                    *(float2*)(outf + o0) = make_float2(v0, v1);
                    *(float2*)(outf + o2) = make_float2(v2, v3);
                } else {
                    *(uint32_t*)(outb + o0) = bf16x2_pack(v0, v1);
                    *(uint32_t*)(outb + o2) = bf16x2_pack(v2, v3);
                }
            }
        }
    }
}

// ---------------- depthwise 3x3, zero pad, bf16 io (R7 known-good) -------------------
__global__ void dwconv_kernel(const __nv_bfloat16* __restrict__ in,
                              const float* __restrict__ w, int C,
                              __nv_bfloat16* __restrict__ out) {
    size_t idx = (size_t)blockIdx.x * blockDim.x + threadIdx.x;
    if (idx >= (size_t)2 * C * HW) return;
    int x = (int)(idx & 127);
    int y = (int)((idx >> 7) & 127);
    int c = (int)((idx >> 14) % C);
    const float* wp = w + c * 9;
    const __nv_bfloat16* ip = in + (idx - (idx & (HW - 1)));
    float acc = 0.f;
    #pragma unroll
    for (int ky = 0; ky < 3; ky++) {
        int yy = y + ky - 1;
        if (yy < 0 || yy > 127) continue;
        #pragma unroll
        for (int kx = 0; kx < 3; kx++) {
            int xx = x + kx - 1;
            if (xx < 0 || xx > 127) continue;
            acc += __bfloat162float(ip[yy * 128 + xx]) * wp[ky * 3 + kx];
        }
    }
    out[idx] = __float2bfloat16(acc);
}

// --------- fused depthwise 3x3 (768ch pair) + gelu gate, bf16 io (R7) ---------------
__global__ void dwconv_gelu_kernel(const __nv_bfloat16* __restrict__ in,
                                   const float* __restrict__ w,
                                   __nv_bfloat16* __restrict__ out) {
    size_t idx = (size_t)blockIdx.x * blockDim.x + threadIdx.x;
    if (idx >= (size_t)2 * 384 * HW) return;
    int x = (int)(idx & 127);
    int y = (int)((idx >> 7) & 127);
    int c = (int)((idx >> 14) % 384);
    int b = (int)(idx / ((size_t)384 * HW));
    const __nv_bfloat16* ip1 = in + ((size_t)b * 768 + c) * HW;
    const __nv_bfloat16* ip2 = ip1 + (size_t)384 * HW;
    const float* w1 = w + c * 9;
    const float* w2 = w + (c + 384) * 9;
    float a1 = 0.f, a2 = 0.f;
    #pragma unroll
    for (int ky = 0; ky < 3; ky++) {
        int yy = y + ky - 1;
        if (yy < 0 || yy > 127) continue;
        #pragma unroll
        for (int kx = 0; kx < 3; kx++) {
            int xx = x + kx - 1;
            if (xx < 0 || xx > 127) continue;
            a1 += __bfloat162float(ip1[yy * 128 + xx]) * w1[ky * 3 + kx];
            a2 += __bfloat162float(ip2[yy * 128 + xx]) * w2[ky * 3 + kx];
        }
    }
    float ge = 0.5f * a1 * (1.0f + erff(a1 * 0.70710678118654752f));
    out[idx] = __float2bfloat16(ge * a2);
}

// ---------------- reciprocal L2 norm over HW per (b, channel), bf16 in --------------
__global__ void rnorm_kernel(const __nv_bfloat16* __restrict__ t, int chtot, int coff,
                             float* __restrict__ rn) {
    int row = blockIdx.x;
    int b = row / 192, c = row % 192;
    const __nv_bfloat16* p = t + ((size_t)b * chtot + coff + c) * HW;
    float s = 0.f;
    for (int i = threadIdx.x; i < HW; i += blockDim.x) {
        float v = __bfloat162float(p[i]); s += v * v;
    }
    __shared__ float red[8];
    #pragma unroll
    for (int o = 16; o; o >>= 1) s += __shfl_down_sync(0xffffffffu, s, o);
    if ((threadIdx.x & 31) == 0) red[threadIdx.x >> 5] = s;
    __syncthreads();
    if (threadIdx.x < 32) {
        s = (threadIdx.x < 8) ? red[threadIdx.x] : 0.f;
        #pragma unroll
        for (int o = 4; o; o >>= 1) s += __shfl_down_sync(0xffffffffu, s, o);
        if (threadIdx.x == 0) rn[row] = 1.0f / fmaxf(sqrtf(s), 1e-12f);
    }
}

// ---------------- q@k^T partials, bf16 in -------------------------------------------
__global__ void qk_kernel(const __nv_bfloat16* __restrict__ q,
                          const __nv_bfloat16* __restrict__ kv,
                          float* __restrict__ Sp) {
    int pc = blockIdx.x, hh = blockIdx.y, b = blockIdx.z;
    const __nv_bfloat16* qb = q  + ((size_t)b * 192 + hh * 32) * HW + pc * 2048;
    const __nv_bfloat16* kb = kv + ((size_t)b * 384 + hh * 32) * HW + pc * 2048;
    __shared__ float sq[32 * 33];
    __shared__ float sk[32 * 33];
    int t = threadIdx.x;
    int i = t & 31, jg = t >> 5;
    float acc[4] = {0.f, 0.f, 0.f, 0.f};
    for (int p0 = 0; p0 < 2048; p0 += 32) {
        #pragma unroll
        for (int l = 0; l < 4; l++) {
            int idx = t + l * 256;
            int r = idx >> 5, cc = idx & 31;
            sq[r * 33 + cc] = __bfloat162float(qb[(size_t)r * HW + p0 + cc]);
            sk[r * 33 + cc] = __bfloat162float(kb[(size_t)r * HW + p0 + cc]);
        }
        __syncthreads();
        #pragma unroll
        for (int p = 0; p < 32; p++) {
            float a = sq[i * 33 + p];
            #pragma unroll
            for (int j = 0; j < 4; j++) acc[j] += a * sk[(jg * 4 + j) * 33 + p];
        }
        __syncthreads();
    }
    float* sp = Sp + (((size_t)(b * 6 + hh) * 8 + pc) * 1024);
    #pragma unroll
    for (int j = 0; j < 4; j++) sp[i * 32 + jg * 4 + j] = acc[j];
}

// ---------------- softmax ------------------------------------------------------------
__global__ void softmax_kernel(const float* __restrict__ Sp, const float* __restrict__ rq,
                               const float* __restrict__ rk, const float* __restrict__ temp,
                               float* __restrict__ attn) {
    int bh = blockIdx.x;
    int b = bh / 6, hh = bh % 6;
    int t = threadIdx.x;
    int i = t >> 5, j = t & 31;
    const float* sp = Sp + (size_t)bh * 8192 + i * 32 + j;
    float s = 0.f;
    #pragma unroll
    for (int pc = 0; pc < 8; pc++) s += sp[pc * 1024];
    s *= rq[b * 192 + hh * 32 + i] * rk[b * 192 + hh * 32 + j] * temp[hh];
    float mx = s;
    #pragma unroll
    for (int o = 16; o; o >>= 1) mx = fmaxf(mx, __shfl_xor_sync(0xffffffffu, mx, o));
    float e = expf(s - mx);
    float sum = e;
    #pragma unroll
    for (int o = 16; o; o >>= 1) sum += __shfl_xor_sync(0xffffffffu, sum, o);
    attn[(size_t)bh * 1024 + i * 32 + j] = e / sum;
}

// ---------------- out = attn @ v, bf16 ----------------------------------------------
__global__ void av_kernel(const float* __restrict__ attn,
                          const __nv_bfloat16* __restrict__ kv,
                          __nv_bfloat16* __restrict__ out) {
    int b = blockIdx.z, hh = blockIdx.y;
    int p = blockIdx.x * 256 + threadIdx.x;
    __shared__ float sA[1024];
    for (int l = threadIdx.x; l < 1024; l += 256)
        sA[l] = attn[(size_t)(b * 6 + hh) * 1024 + l];
    __syncthreads();
    const __nv_bfloat16* vb = kv + ((size_t)b * 384 + 192 + hh * 32) * HW + p;
    float v[32];
    #pragma unroll
    for (int e = 0; e < 32; e++) v[e] = __bfloat162float(vb[(size_t)e * HW]);
    __nv_bfloat16* ob = out + ((size_t)b * 192 + hh * 32) * HW + p;
    #pragma unroll
    for (int i = 0; i < 32; i++) {
        float acc = 0.f;
        #pragma unroll
        for (int e = 0; e < 32; e++) acc += sA[i * 32 + e] * v[e];
        ob[(size_t)i * HW] = __float2bfloat16(acc);
    }
}

// ====================================================================================
extern "C" void kernel_launch(void* const* d_in, const int* in_sizes, int n_in,
                              void* d_out, int out_size) {
    const float* x      = (const float*)d_in[0];
    const float* k_v    = (const float*)d_in[1];
    const float* ln1_w  = (const float*)d_in[2];
    const float* ln1_b  = (const float*)d_in[3];
    const float* temp   = (const float*)d_in[4];
    const float* w_kR   = (const float*)d_in[5];
    const float* w_kI   = (const float*)d_in[6];
    const float* w_qR   = (const float*)d_in[7];
    const float* w_qdw  = (const float*)d_in[8];
    const float* w_kvI  = (const float*)d_in[9];
    const float* w_kvdw = (const float*)d_in[10];
    const float* w_po   = (const float*)d_in[11];
    const float* ln2_w  = (const float*)d_in[12];
    const float* ln2_b  = (const float*)d_in[13];
    const float* w_ffk  = (const float*)d_in[14];
    const float* w_pin  = (const float*)d_in[15];
    const float* w_dw   = (const float*)d_in[16];
    const float* w_pout = (const float*)d_in[17];
    float* out = (float*)d_out;

    float* sc = nullptr;
    cudaGetSymbolAddress((void**)&sc, g_scratch);
    __nv_bfloat16* xs  = (__nv_bfloat16*)(sc + OFF_XS);
    __nv_bfloat16* t1  = (__nv_bfloat16*)(sc + OFF_T1);
    __nv_bfloat16* q   = (__nv_bfloat16*)(sc + OFF_Q);
    __nv_bfloat16* kvp = (__nv_bfloat16*)(sc + OFF_KVP);
    __nv_bfloat16* kvb = (__nv_bfloat16*)(sc + OFF_KVB);
    __nv_bfloat16* yp  = (__nv_bfloat16*)(sc + OFF_YP);
    float* m1  = sc + OFF_M1;
    float* mf  = sc + OFF_MF;
    float* rq  = sc + OFF_RQ;
    float* rk  = sc + OFF_RK;
    float* Sp  = sc + OFF_SP;
    float* att = sc + OFF_ATT;
    uint32_t* wq    = (uint32_t*)(sc + OFF_WQ);
    uint32_t* wkv   = (uint32_t*)(sc + OFF_WKV);
    uint32_t* wpo   = (uint32_t*)(sc + OFF_WPO);
    uint32_t* wpin  = (uint32_t*)(sc + OFF_WPIN);
    uint32_t* wpout = (uint32_t*)(sc + OFF_WPOUT);

    cudaFuncSetAttribute(conv_mma_kernel, cudaFuncAttributeMaxDynamicSharedMemorySize, 73728);
    auto smb = [](int NKC) { return (size_t)NKC * 2048 + 24576; };

    int tail = out_size - 6291456;
    if (tail < 0) tail = 0;
    if (tail > 512) tail = 512;

    // launches 1-3 (launch #4 = conv_q for ncu capture)
    prep_kernel<<<5, 256>>>(k_v, w_kR, w_kI, w_ffk, m1, mf, out + 6291456, tail);
    wpack_all_kernel<<<594, 256>>>(w_qR, w_kvI, w_po, w_pin, w_pout,
                                   wq, wkv, wpo, wpin, wpout);
    ln_scale_kernel<<<128, 256>>>(x, ln1_w, ln1_b, m1, xs);

    // attention branch
    conv_mma_kernel<<<dim3(128, 3), 256, smb(9)>>>(xs, 192, 0, 9, wq, 192, 1,
                                                   nullptr, nullptr, t1);
    conv_mma_kernel<<<dim3(128, 6), 256, smb(3)>>>(xs, 192, 144, 3, wkv, 384, 1,
                                                   nullptr, nullptr, kvp);
    dwconv_kernel<<<(2 * 192 * HW) / 256, 256>>>(t1, w_qdw, 192, q);
    dwconv_kernel<<<(2 * 384 * HW) / 256, 256>>>(kvp, w_kvdw, 384, kvb);
    rnorm_kernel<<<384, 256>>>(q, 192, 0, rq);
    rnorm_kernel<<<384, 256>>>(kvb, 384, 0, rk);
    qk_kernel<<<dim3(8, 6, 2), 256>>>(q, kvb, Sp);
    softmax_kernel<<<12, 1024>>>(Sp, rq, rk, temp, att);
    av_kernel<<<dim3(64, 6, 2), 256>>>(att, kvb, t1);
    conv_mma_kernel<<<dim3(128, 3), 256, smb(12)>>>(t1, 192, 0, 12, wpo, 192, 1,
                                                    x, out, nullptr);

    // GDFN feed-forward
    ln_scale_kernel<<<128, 256>>>(out, ln2_w, ln2_b, mf, xs);
    conv_mma_kernel<<<dim3(64, 12), 256, smb(12)>>>(xs, 192, 0, 12, wpin, 768, 2,
                                                    nullptr, nullptr, yp);
    dwconv_gelu_kernel<<<(2 * 384 * HW) / 256, 256>>>(yp, w_dw, kvp);
    conv_mma_kernel<<<dim3(128, 3), 256, smb(24)>>>(kvp, 384, 0, 24, wpout, 192, 1,
                                                    out, out, nullptr);
}

// round 10
// speedup vs baseline: 1.3824x; 1.1307x over previous
#include <cuda_runtime.h>
#include <cuda_bf16.h>
#include <stdint.h>
#include <math.h>

#define HW 16384

// ---------------- helpers ----------------
__device__ __forceinline__ uint32_t smem_u32(const void* p) {
    uint32_t a;
    asm("{ .reg .u64 t; cvta.to.shared.u64 t, %1; cvt.u32.u64 %0, t; }" : "=r"(a) : "l"(p));
    return a;
}
__device__ __forceinline__ void cp_async16(uint32_t dst, const void* src) {
    asm volatile("cp.async.cg.shared.global [%0], [%1], 16;" :: "r"(dst), "l"(src));
}
#define CP_COMMIT() asm volatile("cp.async.commit_group;" ::: "memory")
#define CP_WAIT0()  asm volatile("cp.async.wait_group 0;" ::: "memory")
#define CP_WAIT1()  asm volatile("cp.async.wait_group 1;" ::: "memory")
#define CP_WAIT2()  asm volatile("cp.async.wait_group 2;" ::: "memory")
#define CP_WAIT3()  asm volatile("cp.async.wait_group 3;" ::: "memory")

__device__ __forceinline__ uint32_t bf16x2_pack(float lo, float hi) {
    uint32_t r;
    asm("cvt.rn.bf16x2.f32 %0, %1, %2;" : "=r"(r) : "f"(hi), "f"(lo));
    return r;
}
__device__ __forceinline__ void ldmatrix_x4_trans(uint32_t* r, uint32_t addr) {
    asm volatile("ldmatrix.sync.aligned.m8n8.x4.trans.shared.b16 {%0,%1,%2,%3}, [%4];"
                 : "=r"(r[0]), "=r"(r[1]), "=r"(r[2]), "=r"(r[3]) : "r"(addr));
}
__device__ __forceinline__ void mma_bf16(float* d, const uint32_t* a, uint32_t b0, uint32_t b1) {
    asm("mma.sync.aligned.m16n8k16.row.col.f32.bf16.bf16.f32 "
        "{%0,%1,%2,%3},{%4,%5,%6,%7},{%8,%9},{%0,%1,%2,%3};"
        : "+f"(d[0]), "+f"(d[1]), "+f"(d[2]), "+f"(d[3])
        : "r"(a[0]), "r"(a[1]), "r"(a[2]), "r"(a[3]), "r"(b0), "r"(b1));
}

// ---------------- scratch (float units) ----------------
#define OFF_XS     0ULL           // bf16 [2,192,HW]
#define OFF_T1     3145728ULL     // bf16 [2,192,HW]
#define OFF_Q      6291456ULL     // bf16 [2,192,HW]
#define OFF_KVP    9437184ULL     // bf16 [2,384,HW]
#define OFF_KVB    15728640ULL    // bf16 [2,384,HW]
#define OFF_YP     22020096ULL    // bf16 [2,768,HW]
#define OFF_M1     34603008ULL
#define OFF_MF     34603392ULL
#define OFF_RQ     34603776ULL
#define OFF_RK     34604160ULL
#define OFF_SP     34604544ULL    // fp32 [2,6,32,32,32]
#define OFF_ATT    34997760ULL    // fp32 [2,6,32,32]
#define OFF_WQ     35010048ULL    // u32 13824
#define OFF_WKV    35023872ULL    // u32 9216
#define OFF_WPO    35033088ULL    // u32 18432
#define OFF_WPIN   35051520ULL    // u32 73728
#define OFF_WPOUT  35125248ULL    // u32 36864
#define SCRATCH_TOTAL 35162112ULL
__device__ float g_scratch[SCRATCH_TOTAL];

// ---------------- prep: per-batch channel multipliers + k_v tail --------------------
__global__ void prep_kernel(const float* __restrict__ kv, const float* __restrict__ wkR,
                            const float* __restrict__ wkI, const float* __restrict__ wffk,
                            float* __restrict__ m1, float* __restrict__ mf,
                            float* __restrict__ out_tail, int tail) {
    int t = blockIdx.x * blockDim.x + threadIdx.x;
    if (t < 384) {
        int b = t / 192, c = t % 192;
        float acc = 1.0f;
        if (c < 144) {
            const float* w = wkR + c * 192; const float* v = kv + b * 256;
            for (int i = 0; i < 192; i++) acc += w[i] * v[i];
        } else {
            const float* w = wkI + (c - 144) * 64; const float* v = kv + b * 256 + 192;
            for (int i = 0; i < 64; i++) acc += w[i] * v[i];
        }
        m1[t] = acc;
    } else if (t < 768) {
        int u = t - 384; int b = u / 192, c = u % 192;
        float acc = 1.0f;
        const float* w = wffk + c * 256; const float* v = kv + b * 256;
        for (int i = 0; i < 256; i++) acc += w[i] * v[i];
        mf[u] = acc;
    } else if (t - 768 < tail) {
        out_tail[t - 768] = kv[t - 768];
    }
}

// ------- pack weights W[oc][ic] into bf16 A-fragment order (u32 = bf16x2) -----------
__device__ __forceinline__ void pack_one(const float* __restrict__ W, int ic, int NKC,
                                         uint32_t* __restrict__ pack, int idx) {
    int reg = idx & 3, lane = (idx >> 2) & 31, mi = (idx >> 7) & 3;
    int kc = (idx >> 9) % NKC, ocb = (idx >> 9) / NKC;
    int g = lane >> 2, tig = lane & 3;
    int oc = ocb * 64 + mi * 16 + g + (reg & 1) * 8;
    int k = kc * 16 + tig * 2 + (reg >> 1) * 8;
    pack[idx] = bf16x2_pack(W[(size_t)oc * ic + k], W[(size_t)oc * ic + k + 1]);
}

__global__ void wpack_all_kernel(const float* __restrict__ wq, const float* __restrict__ wkv,
                                 const float* __restrict__ wpo, const float* __restrict__ wpin,
                                 const float* __restrict__ wpout,
                                 uint32_t* __restrict__ pq, uint32_t* __restrict__ pkv,
                                 uint32_t* __restrict__ ppo, uint32_t* __restrict__ ppin,
                                 uint32_t* __restrict__ ppout) {
    int idx = blockIdx.x * 256 + threadIdx.x;
    if (idx < 13824)        pack_one(wq,    144,  9, pq,    idx);
    else if (idx < 23040)   pack_one(wkv,    48,  3, pkv,   idx - 13824);
    else if (idx < 41472)   pack_one(wpo,   192, 12, ppo,   idx - 23040);
    else if (idx < 115200)  pack_one(wpin,  192, 12, ppin,  idx - 41472);
    else if (idx < 152064)  pack_one(wpout, 384, 24, ppout, idx - 115200);
}

// ------- channel LayerNorm * mult -> bf16, channel-split (512 thr, 128 px/block) -----
__global__ void __launch_bounds__(512) ln_scale_kernel(
        const float* __restrict__ x, const float* __restrict__ w,
        const float* __restrict__ bias, const float* __restrict__ m,
        __nv_bfloat16* __restrict__ out) {
    __shared__ float s1s[4][128];
    __shared__ float s2s[4][128];
    int tid = threadIdx.x;
    int pxl = tid & 127, cg = tid >> 7;        // cg 0..3 -> channels cg*48..+48
    int p = blockIdx.x * 128 + pxl;
    int b = p >> 14, px = p & (HW - 1);
    const float* xb = x + ((size_t)b * 192 + cg * 48) * HW + px;
    float s = 0.f, s2 = 0.f;
    #pragma unroll 8
    for (int c = 0; c < 48; c++) { float v = xb[(size_t)c * HW]; s += v; s2 += v * v; }
    s1s[cg][pxl] = s; s2s[cg][pxl] = s2;
    __syncthreads();
    float st = s1s[0][pxl] + s1s[1][pxl] + s1s[2][pxl] + s1s[3][pxl];
    float s2t = s2s[0][pxl] + s2s[1][pxl] + s2s[2][pxl] + s2s[3][pxl];
    float mu = st * (1.0f / 192.0f);
    float rstd = rsqrtf(s2t * (1.0f / 192.0f) - mu * mu + 1e-5f);
    __nv_bfloat16* ob = out + ((size_t)b * 192 + cg * 48) * HW + px;
    const float* wg = w + cg * 48;
    const float* bg = bias + cg * 48;
    const float* mg = m + b * 192 + cg * 48;
    #pragma unroll 8
    for (int c = 0; c < 48; c++) {
        float v = (xb[(size_t)c * HW] - mu) * rstd * wg[c] + bg[c];
        ob[(size_t)c * HW] = __float2bfloat16(v * mg[c]);
    }
}

// ------- bf16 mma.sync conv1x1, warp-autonomous, 4-stage cp.async pipeline -----------
__global__ void __launch_bounds__(256) conv_mma_kernel(
        const __nv_bfloat16* __restrict__ in, int ictot, int icoff, int NKC,
        const uint32_t* __restrict__ wpack, int octot, int tpc,
        const float* __restrict__ res, float* __restrict__ outf,
        __nv_bfloat16* __restrict__ outb) {
    extern __shared__ char sm[];
    char* sIn = sm + NKC * 2048;                 // 8 warps x 4 bufs x 1KB
    int tid = threadIdx.x, wid = tid >> 5, lane = tid & 31;
    int g = lane >> 2, tig = lane & 3;
    int ocbase = blockIdx.y * 64;

    {   // resident packed A-weights for this 64-oc slice
        const uint4* gw = (const uint4*)(wpack + (size_t)blockIdx.y * NKC * 512);
        uint4* sw4 = (uint4*)sm;
        for (int i = tid; i < NKC * 128; i += 256) sw4[i] = gw[i];
    }
    __syncthreads();

    uint32_t wInb = smem_u32(sIn) + (uint32_t)wid * 4096u;
    int lm = lane >> 3, lr = lane & 7;
    uint32_t lmrow = (uint32_t)(((lm & 1) * 8 + lr) * 64 + (lm >> 1) * 16);
    int ldr = lane >> 2, ldc = lane & 3;

    for (int t = 0; t < tpc; t++) {
        int pxg = (blockIdx.x * tpc + t) * 256;
        int b = pxg >> 14, pxb = pxg & (HW - 1);
        const __nv_bfloat16* gin = in + ((size_t)b * ictot + icoff) * HW + pxb + wid * 32;

        // prologue: chunks 0..2 -> bufs 0..2 (NKC >= 3 always)
        #pragma unroll
        for (int pc = 0; pc < 3; pc++) {
            const __nv_bfloat16* src = gin + (size_t)pc * 16 * HW;
            uint32_t dstb = wInb + (uint32_t)pc * 1024u;
            #pragma unroll
            for (int i = 0; i < 2; i++) {
                int r = ldr + 8 * i;
                cp_async16(dstb + (uint32_t)(r * 64 + ldc * 16), src + (size_t)r * HW + ldc * 8);
            }
            CP_COMMIT();
        }

        float d[4][4][4];
        #pragma unroll
        for (int mi = 0; mi < 4; mi++)
            #pragma unroll
            for (int ni = 0; ni < 4; ni++)
                #pragma unroll
                for (int r = 0; r < 4; r++) d[mi][ni][r] = 0.f;

        for (int kc = 0; kc < NKC; kc++) {
            if (kc + 3 < NKC) {
                const __nv_bfloat16* src = gin + (size_t)(kc + 3) * 16 * HW;
                uint32_t dstb = wInb + (uint32_t)((kc + 3) & 3) * 1024u;
                #pragma unroll
                for (int i = 0; i < 2; i++) {
                    int r = ldr + 8 * i;
                    cp_async16(dstb + (uint32_t)(r * 64 + ldc * 16), src + (size_t)r * HW + ldc * 8);
                }
                CP_COMMIT();
                CP_WAIT3();
            } else if (kc + 2 < NKC) {
                CP_WAIT2();
            } else if (kc + 1 < NKC) {
                CP_WAIT1();
            } else {
                CP_WAIT0();
            }
            __syncwarp();

            uint32_t bufb = wInb + (uint32_t)(kc & 3) * 1024u;
            uint32_t bfr[2][4];
            ldmatrix_x4_trans(bfr[0], bufb + lmrow);
            ldmatrix_x4_trans(bfr[1], bufb + lmrow + 32);

            const uint4* wk = (const uint4*)(sm + kc * 2048);
            #pragma unroll
            for (int mi = 0; mi < 4; mi++) {
                uint4 av4 = wk[mi * 32 + lane];
                uint32_t a[4] = {av4.x, av4.y, av4.z, av4.w};
                mma_bf16(d[mi][0], a, bfr[0][0], bfr[0][1]);
                mma_bf16(d[mi][1], a, bfr[0][2], bfr[0][3]);
                mma_bf16(d[mi][2], a, bfr[1][0], bfr[1][1]);
                mma_bf16(d[mi][3], a, bfr[1][2], bfr[1][3]);
            }
        }

        #pragma unroll
        for (int mi = 0; mi < 4; mi++) {
            int oc0 = ocbase + mi * 16 + g;
            #pragma unroll
            for (int ni = 0; ni < 4; ni++) {
                int px0 = pxb + wid * 32 + ni * 8 + tig * 2;
                size_t o0 = ((size_t)b * octot + oc0) * HW + px0;
                size_t o2 = o0 + (size_t)8 * HW;
                float v0 = d[mi][ni][0], v1 = d[mi][ni][1];
                float v2 = d[mi][ni][2], v3 = d[mi][ni][3];
                if (outf) {
                    if (res) {
                        float2 e0 = *(const float2*)(res + o0);
                        float2 e2 = *(const float2*)(res + o2);
                        v0 += e0.x; v1 += e0.y; v2 += e2.x; v3 += e2.y;
                    }
                    *(float2*)(outf + o0) = make_float2(v0, v1);
                    *(float2*)(outf + o2) = make_float2(v2, v3);
                } else {
                    *(uint32_t*)(outb + o0) = bf16x2_pack(v0, v1);
                    *(uint32_t*)(outb + o2) = bf16x2_pack(v2, v3);
                }
            }
        }
    }
}

// ---------------- depthwise 3x3, zero pad, bf16 io -----------------------------------
__global__ void dwconv_kernel(const __nv_bfloat16* __restrict__ in,
                              const float* __restrict__ w, int C,
                              __nv_bfloat16* __restrict__ out) {
    size_t idx = (size_t)blockIdx.x * blockDim.x + threadIdx.x;
    if (idx >= (size_t)2 * C * HW) return;
    int x = (int)(idx & 127);
    int y = (int)((idx >> 7) & 127);
    int c = (int)((idx >> 14) % C);
    const float* wp = w + c * 9;
    const __nv_bfloat16* ip = in + (idx - (idx & (HW - 1)));
    float acc = 0.f;
    #pragma unroll
    for (int ky = 0; ky < 3; ky++) {
        int yy = y + ky - 1;
        if (yy < 0 || yy > 127) continue;
        #pragma unroll
        for (int kx = 0; kx < 3; kx++) {
            int xx = x + kx - 1;
            if (xx < 0 || xx > 127) continue;
            acc += __bfloat162float(ip[yy * 128 + xx]) * wp[ky * 3 + kx];
        }
    }
    out[idx] = __float2bfloat16(acc);
}

// --------- fused depthwise 3x3 (768ch pair) + gelu gate, bf16 io --------------------
__global__ void dwconv_gelu_kernel(const __nv_bfloat16* __restrict__ in,
                                   const float* __restrict__ w,
                                   __nv_bfloat16* __restrict__ out) {
    size_t idx = (size_t)blockIdx.x * blockDim.x + threadIdx.x;
    if (idx >= (size_t)2 * 384 * HW) return;
    int x = (int)(idx & 127);
    int y = (int)((idx >> 7) & 127);
    int c = (int)((idx >> 14) % 384);
    int b = (int)(idx / ((size_t)384 * HW));
    const __nv_bfloat16* ip1 = in + ((size_t)b * 768 + c) * HW;
    const __nv_bfloat16* ip2 = ip1 + (size_t)384 * HW;
    const float* w1 = w + c * 9;
    const float* w2 = w + (c + 384) * 9;
    float a1 = 0.f, a2 = 0.f;
    #pragma unroll
    for (int ky = 0; ky < 3; ky++) {
        int yy = y + ky - 1;
        if (yy < 0 || yy > 127) continue;
        #pragma unroll
        for (int kx = 0; kx < 3; kx++) {
            int xx = x + kx - 1;
            if (xx < 0 || xx > 127) continue;
            a1 += __bfloat162float(ip1[yy * 128 + xx]) * w1[ky * 3 + kx];
            a2 += __bfloat162float(ip2[yy * 128 + xx]) * w2[ky * 3 + kx];
        }
    }
    float ge = 0.5f * a1 * (1.0f + erff(a1 * 0.70710678118654752f));
    out[idx] = __float2bfloat16(ge * a2);
}

// ---------------- reciprocal L2 norm over HW per (b, channel), bf16 in --------------
__global__ void rnorm_kernel(const __nv_bfloat16* __restrict__ t, int chtot, int coff,
                             float* __restrict__ rn) {
    int row = blockIdx.x;
    int b = row / 192, c = row % 192;
    const __nv_bfloat16* p = t + ((size_t)b * chtot + coff + c) * HW;
    float s = 0.f;
    for (int i = threadIdx.x; i < HW; i += blockDim.x) {
        float v = __bfloat162float(p[i]); s += v * v;
    }
    __shared__ float red[8];
    #pragma unroll
    for (int o = 16; o; o >>= 1) s += __shfl_down_sync(0xffffffffu, s, o);
    if ((threadIdx.x & 31) == 0) red[threadIdx.x >> 5] = s;
    __syncthreads();
    if (threadIdx.x < 32) {
        s = (threadIdx.x < 8) ? red[threadIdx.x] : 0.f;
        #pragma unroll
        for (int o = 4; o; o >>= 1) s += __shfl_down_sync(0xffffffffu, s, o);
        if (threadIdx.x == 0) rn[row] = 1.0f / fmaxf(sqrtf(s), 1e-12f);
    }
}

// ---------------- q@k^T partials, bf16 in, 32 px-chunks of 512 ----------------------
__global__ void qk_kernel(const __nv_bfloat16* __restrict__ q,
                          const __nv_bfloat16* __restrict__ kv,
                          float* __restrict__ Sp) {
    int pc = blockIdx.x, hh = blockIdx.y, b = blockIdx.z;
    const __nv_bfloat16* qb = q  + ((size_t)b * 192 + hh * 32) * HW + pc * 512;
    const __nv_bfloat16* kb = kv + ((size_t)b * 384 + hh * 32) * HW + pc * 512;
    __shared__ float sq[32 * 33];
    __shared__ float sk[32 * 33];
    int t = threadIdx.x;
    int i = t & 31, jg = t >> 5;
    float acc[4] = {0.f, 0.f, 0.f, 0.f};
    for (int p0 = 0; p0 < 512; p0 += 32) {
        #pragma unroll
        for (int l = 0; l < 4; l++) {
            int idx = t + l * 256;
            int r = idx >> 5, cc = idx & 31;
            sq[r * 33 + cc] = __bfloat162float(qb[(size_t)r * HW + p0 + cc]);
            sk[r * 33 + cc] = __bfloat162float(kb[(size_t)r * HW + p0 + cc]);
        }
        __syncthreads();
        #pragma unroll
        for (int p = 0; p < 32; p++) {
            float a = sq[i * 33 + p];
            #pragma unroll
            for (int j = 0; j < 4; j++) acc[j] += a * sk[(jg * 4 + j) * 33 + p];
        }
        __syncthreads();
    }
    float* sp = Sp + (((size_t)(b * 6 + hh) * 32 + pc) * 1024);
    #pragma unroll
    for (int j = 0; j < 4; j++) sp[i * 32 + jg * 4 + j] = acc[j];
}

// ---------------- softmax (sums 32 partials) ------------------------------------------
__global__ void softmax_kernel(const float* __restrict__ Sp, const float* __restrict__ rq,
                               const float* __restrict__ rk, const float* __restrict__ temp,
                               float* __restrict__ attn) {
    int bh = blockIdx.x;
    int b = bh / 6, hh = bh % 6;
    int t = threadIdx.x;
    int i = t >> 5, j = t & 31;
    const float* sp = Sp + (size_t)bh * 32768 + i * 32 + j;
    float s = 0.f;
    #pragma unroll
    for (int pc = 0; pc < 32; pc++) s += sp[pc * 1024];
    s *= rq[b * 192 + hh * 32 + i] * rk[b * 192 + hh * 32 + j] * temp[hh];
    float mx = s;
    #pragma unroll
    for (int o = 16; o; o >>= 1) mx = fmaxf(mx, __shfl_xor_sync(0xffffffffu, mx, o));
    float e = expf(s - mx);
    float sum = e;
    #pragma unroll
    for (int o = 16; o; o >>= 1) sum += __shfl_xor_sync(0xffffffffu, sum, o);
    attn[(size_t)bh * 1024 + i * 32 + j] = e / sum;
}

// ---------------- out = attn @ v, bf16 ----------------------------------------------
__global__ void av_kernel(const float* __restrict__ attn,
                          const __nv_bfloat16* __restrict__ kv,
                          __nv_bfloat16* __restrict__ out) {
    int b = blockIdx.z, hh = blockIdx.y;
    int p = blockIdx.x * 256 + threadIdx.x;
    __shared__ float sA[1024];
    for (int l = threadIdx.x; l < 1024; l += 256)
        sA[l] = attn[(size_t)(b * 6 + hh) * 1024 + l];
    __syncthreads();
    const __nv_bfloat16* vb = kv + ((size_t)b * 384 + 192 + hh * 32) * HW + p;
    float v[32];
    #pragma unroll
    for (int e = 0; e < 32; e++) v[e] = __bfloat162float(vb[(size_t)e * HW]);
    __nv_bfloat16* ob = out + ((size_t)b * 192 + hh * 32) * HW + p;
    #pragma unroll
    for (int i = 0; i < 32; i++) {
        float acc = 0.f;
        #pragma unroll
        for (int e = 0; e < 32; e++) acc += sA[i * 32 + e] * v[e];
        ob[(size_t)i * HW] = __float2bfloat16(acc);
    }
}

// ====================================================================================
extern "C" void kernel_launch(void* const* d_in, const int* in_sizes, int n_in,
                              void* d_out, int out_size) {
    const float* x      = (const float*)d_in[0];
    const float* k_v    = (const float*)d_in[1];
    const float* ln1_w  = (const float*)d_in[2];
    const float* ln1_b  = (const float*)d_in[3];
    const float* temp   = (const float*)d_in[4];
    const float* w_kR   = (const float*)d_in[5];
    const float* w_kI   = (const float*)d_in[6];
    const float* w_qR   = (const float*)d_in[7];
    const float* w_qdw  = (const float*)d_in[8];
    const float* w_kvI  = (const float*)d_in[9];
    const float* w_kvdw = (const float*)d_in[10];
    const float* w_po   = (const float*)d_in[11];
    const float* ln2_w  = (const float*)d_in[12];
    const float* ln2_b  = (const float*)d_in[13];
    const float* w_ffk  = (const float*)d_in[14];
    const float* w_pin  = (const float*)d_in[15];
    const float* w_dw   = (const float*)d_in[16];
    const float* w_pout = (const float*)d_in[17];
    float* out = (float*)d_out;

    float* sc = nullptr;
    cudaGetSymbolAddress((void**)&sc, g_scratch);
    __nv_bfloat16* xs  = (__nv_bfloat16*)(sc + OFF_XS);
    __nv_bfloat16* t1  = (__nv_bfloat16*)(sc + OFF_T1);
    __nv_bfloat16* q   = (__nv_bfloat16*)(sc + OFF_Q);
    __nv_bfloat16* kvp = (__nv_bfloat16*)(sc + OFF_KVP);
    __nv_bfloat16* kvb = (__nv_bfloat16*)(sc + OFF_KVB);
    __nv_bfloat16* yp  = (__nv_bfloat16*)(sc + OFF_YP);
    float* m1  = sc + OFF_M1;
    float* mf  = sc + OFF_MF;
    float* rq  = sc + OFF_RQ;
    float* rk  = sc + OFF_RK;
    float* Sp  = sc + OFF_SP;
    float* att = sc + OFF_ATT;
    uint32_t* wq    = (uint32_t*)(sc + OFF_WQ);
    uint32_t* wkv   = (uint32_t*)(sc + OFF_WKV);
    uint32_t* wpo   = (uint32_t*)(sc + OFF_WPO);
    uint32_t* wpin  = (uint32_t*)(sc + OFF_WPIN);
    uint32_t* wpout = (uint32_t*)(sc + OFF_WPOUT);

    cudaFuncSetAttribute(conv_mma_kernel, cudaFuncAttributeMaxDynamicSharedMemorySize, 81920);
    auto smb = [](int NKC) { return (size_t)NKC * 2048 + 32768; };

    int tail = out_size - 6291456;
    if (tail < 0) tail = 0;
    if (tail > 512) tail = 512;

    // launches 1-3 (launch #4 = conv_q for ncu capture)
    prep_kernel<<<5, 256>>>(k_v, w_kR, w_kI, w_ffk, m1, mf, out + 6291456, tail);
    wpack_all_kernel<<<594, 256>>>(w_qR, w_kvI, w_po, w_pin, w_pout,
                                   wq, wkv, wpo, wpin, wpout);
    ln_scale_kernel<<<256, 512>>>(x, ln1_w, ln1_b, m1, xs);

    // attention branch
    conv_mma_kernel<<<dim3(128, 3), 256, smb(9)>>>(xs, 192, 0, 9, wq, 192, 1,
                                                   nullptr, nullptr, t1);
    conv_mma_kernel<<<dim3(128, 6), 256, smb(3)>>>(xs, 192, 144, 3, wkv, 384, 1,
                                                   nullptr, nullptr, kvp);
    dwconv_kernel<<<(2 * 192 * HW) / 256, 256>>>(t1, w_qdw, 192, q);
    dwconv_kernel<<<(2 * 384 * HW) / 256, 256>>>(kvp, w_kvdw, 384, kvb);
    rnorm_kernel<<<384, 256>>>(q, 192, 0, rq);
    rnorm_kernel<<<384, 256>>>(kvb, 384, 0, rk);
    qk_kernel<<<dim3(32, 6, 2), 256>>>(q, kvb, Sp);
    softmax_kernel<<<12, 1024>>>(Sp, rq, rk, temp, att);
    av_kernel<<<dim3(64, 6, 2), 256>>>(att, kvb, t1);
    conv_mma_kernel<<<dim3(128, 3), 256, smb(12)>>>(t1, 192, 0, 12, wpo, 192, 1,
                                                    x, out, nullptr);

    // GDFN feed-forward
    ln_scale_kernel<<<256, 512>>>(out, ln2_w, ln2_b, mf, xs);
    conv_mma_kernel<<<dim3(128, 12), 256, smb(12)>>>(xs, 192, 0, 12, wpin, 768, 1,
                                                     nullptr, nullptr, yp);
    dwconv_gelu_kernel<<<(2 * 384 * HW) / 256, 256>>>(yp, w_dw, kvp);
    conv_mma_kernel<<<dim3(128, 3), 256, smb(24)>>>(kvp, 384, 0, 24, wpout, 192, 1,
                                                    out, out, nullptr);
}

// round 11
// speedup vs baseline: 1.9091x; 1.3810x over previous
#include <cuda_runtime.h>
#include <cuda_bf16.h>
#include <stdint.h>
#include <math.h>

#define HW 16384

// ---------------- helpers ----------------
__device__ __forceinline__ uint32_t smem_u32(const void* p) {
    uint32_t a;
    asm("{ .reg .u64 t; cvta.to.shared.u64 t, %1; cvt.u32.u64 %0, t; }" : "=r"(a) : "l"(p));
    return a;
}
__device__ __forceinline__ void cp_async16(uint32_t dst, const void* src) {
    asm volatile("cp.async.cg.shared.global [%0], [%1], 16;" :: "r"(dst), "l"(src));
}
#define CP_COMMIT() asm volatile("cp.async.commit_group;" ::: "memory")
#define CP_WAIT0()  asm volatile("cp.async.wait_group 0;" ::: "memory")
#define CP_WAIT1()  asm volatile("cp.async.wait_group 1;" ::: "memory")
#define CP_WAIT2()  asm volatile("cp.async.wait_group 2;" ::: "memory")
#define CP_WAIT3()  asm volatile("cp.async.wait_group 3;" ::: "memory")

__device__ __forceinline__ uint32_t bf16x2_pack(float lo, float hi) {
    uint32_t r;
    asm("cvt.rn.bf16x2.f32 %0, %1, %2;" : "=r"(r) : "f"(hi), "f"(lo));
    return r;
}
__device__ __forceinline__ void ldmatrix_x4_trans(uint32_t* r, uint32_t addr) {
    asm volatile("ldmatrix.sync.aligned.m8n8.x4.trans.shared.b16 {%0,%1,%2,%3}, [%4];"
                 : "=r"(r[0]), "=r"(r[1]), "=r"(r[2]), "=r"(r[3]) : "r"(addr));
}
__device__ __forceinline__ void mma_bf16(float* d, const uint32_t* a, uint32_t b0, uint32_t b1) {
    asm("mma.sync.aligned.m16n8k16.row.col.f32.bf16.bf16.f32 "
        "{%0,%1,%2,%3},{%4,%5,%6,%7},{%8,%9},{%0,%1,%2,%3};"
        : "+f"(d[0]), "+f"(d[1]), "+f"(d[2]), "+f"(d[3])
        : "r"(a[0]), "r"(a[1]), "r"(a[2]), "r"(a[3]), "r"(b0), "r"(b1));
}

// ---------------- scratch (float units) ----------------
#define OFF_XS     0ULL           // bf16 [2,192,HW]
#define OFF_T1     3145728ULL     // bf16 [2,192,HW]
#define OFF_Q      6291456ULL     // bf16 [2,192,HW]
#define OFF_KVP    9437184ULL     // bf16 [2,384,HW]
#define OFF_KVB    15728640ULL    // bf16 [2,384,HW]
#define OFF_YP     22020096ULL    // bf16 [2,768,HW]
#define OFF_M1     34603008ULL
#define OFF_MF     34603392ULL
#define OFF_RQ     34603776ULL
#define OFF_RK     34604160ULL
#define OFF_SP     34604544ULL    // fp32 [2,6,32,32,32]
#define OFF_ATT    34997760ULL    // fp32 [2,6,32,32]
#define OFF_WQ     35010048ULL    // u32 13824
#define OFF_WKV    35023872ULL    // u32 9216
#define OFF_WPO    35033088ULL    // u32 18432
#define OFF_WPIN   35051520ULL    // u32 73728
#define OFF_WPOUT  35125248ULL    // u32 36864
#define SCRATCH_TOTAL 35162112ULL
__device__ float g_scratch[SCRATCH_TOTAL];

// ---------------- prep: per-batch channel multipliers + k_v tail --------------------
__global__ void prep_kernel(const float* __restrict__ kv, const float* __restrict__ wkR,
                            const float* __restrict__ wkI, const float* __restrict__ wffk,
                            float* __restrict__ m1, float* __restrict__ mf,
                            float* __restrict__ out_tail, int tail) {
    int t = blockIdx.x * blockDim.x + threadIdx.x;
    if (t < 384) {
        int b = t / 192, c = t % 192;
        float acc = 1.0f;
        if (c < 144) {
            const float* w = wkR + c * 192; const float* v = kv + b * 256;
            for (int i = 0; i < 192; i++) acc += w[i] * v[i];
        } else {
            const float* w = wkI + (c - 144) * 64; const float* v = kv + b * 256 + 192;
            for (int i = 0; i < 64; i++) acc += w[i] * v[i];
        }
        m1[t] = acc;
    } else if (t < 768) {
        int u = t - 384; int b = u / 192, c = u % 192;
        float acc = 1.0f;
        const float* w = wffk + c * 256; const float* v = kv + b * 256;
        for (int i = 0; i < 256; i++) acc += w[i] * v[i];
        mf[u] = acc;
    } else if (t - 768 < tail) {
        out_tail[t - 768] = kv[t - 768];
    }
}

// ------- pack weights W[oc][ic] into bf16 A-fragment order (u32 = bf16x2) -----------
__device__ __forceinline__ void pack_one(const float* __restrict__ W, int ic, int NKC,
                                         uint32_t* __restrict__ pack, int idx) {
    int reg = idx & 3, lane = (idx >> 2) & 31, mi = (idx >> 7) & 3;
    int kc = (idx >> 9) % NKC, ocb = (idx >> 9) / NKC;
    int g = lane >> 2, tig = lane & 3;
    int oc = ocb * 64 + mi * 16 + g + (reg & 1) * 8;
    int k = kc * 16 + tig * 2 + (reg >> 1) * 8;
    pack[idx] = bf16x2_pack(W[(size_t)oc * ic + k], W[(size_t)oc * ic + k + 1]);
}

__global__ void wpack_all_kernel(const float* __restrict__ wq, const float* __restrict__ wkv,
                                 const float* __restrict__ wpo, const float* __restrict__ wpin,
                                 const float* __restrict__ wpout,
                                 uint32_t* __restrict__ pq, uint32_t* __restrict__ pkv,
                                 uint32_t* __restrict__ ppo, uint32_t* __restrict__ ppin,
                                 uint32_t* __restrict__ ppout) {
    int idx = blockIdx.x * 256 + threadIdx.x;
    if (idx < 13824)        pack_one(wq,    144,  9, pq,    idx);
    else if (idx < 23040)   pack_one(wkv,    48,  3, pkv,   idx - 13824);
    else if (idx < 41472)   pack_one(wpo,   192, 12, ppo,   idx - 23040);
    else if (idx < 115200)  pack_one(wpin,  192, 12, ppin,  idx - 41472);
    else if (idx < 152064)  pack_one(wpout, 384, 24, ppout, idx - 115200);
}

// ------- channel LayerNorm * mult -> bf16, channel-split (512 thr, 128 px/block) -----
__global__ void __launch_bounds__(512) ln_scale_kernel(
        const float* __restrict__ x, const float* __restrict__ w,
        const float* __restrict__ bias, const float* __restrict__ m,
        __nv_bfloat16* __restrict__ out) {
    __shared__ float s1s[4][128];
    __shared__ float s2s[4][128];
    int tid = threadIdx.x;
    int pxl = tid & 127, cg = tid >> 7;
    int p = blockIdx.x * 128 + pxl;
    int b = p >> 14, px = p & (HW - 1);
    const float* xb = x + ((size_t)b * 192 + cg * 48) * HW + px;
    float s = 0.f, s2 = 0.f;
    #pragma unroll 8
    for (int c = 0; c < 48; c++) { float v = xb[(size_t)c * HW]; s += v; s2 += v * v; }
    s1s[cg][pxl] = s; s2s[cg][pxl] = s2;
    __syncthreads();
    float st = s1s[0][pxl] + s1s[1][pxl] + s1s[2][pxl] + s1s[3][pxl];
    float s2t = s2s[0][pxl] + s2s[1][pxl] + s2s[2][pxl] + s2s[3][pxl];
    float mu = st * (1.0f / 192.0f);
    float rstd = rsqrtf(s2t * (1.0f / 192.0f) - mu * mu + 1e-5f);
    __nv_bfloat16* ob = out + ((size_t)b * 192 + cg * 48) * HW + px;
    const float* wg = w + cg * 48;
    const float* bg = bias + cg * 48;
    const float* mg = m + b * 192 + cg * 48;
    #pragma unroll 8
    for (int c = 0; c < 48; c++) {
        float v = (xb[(size_t)c * HW] - mu) * rstd * wg[c] + bg[c];
        ob[(size_t)c * HW] = __float2bfloat16(v * mg[c]);
    }
}

// ------- bf16 mma.sync conv1x1, warp-autonomous, 4-stage cp.async pipeline -----------
__global__ void __launch_bounds__(256) conv_mma_kernel(
        const __nv_bfloat16* __restrict__ in, int ictot, int icoff, int NKC,
        const uint32_t* __restrict__ wpack, int octot, int tpc,
        const float* __restrict__ res, float* __restrict__ outf,
        __nv_bfloat16* __restrict__ outb) {
    extern __shared__ char sm[];
    char* sIn = sm + NKC * 2048;
    int tid = threadIdx.x, wid = tid >> 5, lane = tid & 31;
    int g = lane >> 2, tig = lane & 3;
    int ocbase = blockIdx.y * 64;

    {
        const uint4* gw = (const uint4*)(wpack + (size_t)blockIdx.y * NKC * 512);
        uint4* sw4 = (uint4*)sm;
        for (int i = tid; i < NKC * 128; i += 256) sw4[i] = gw[i];
    }
    __syncthreads();

    uint32_t wInb = smem_u32(sIn) + (uint32_t)wid * 4096u;
    int lm = lane >> 3, lr = lane & 7;
    uint32_t lmrow = (uint32_t)(((lm & 1) * 8 + lr) * 64 + (lm >> 1) * 16);
    int ldr = lane >> 2, ldc = lane & 3;

    for (int t = 0; t < tpc; t++) {
        int pxg = (blockIdx.x * tpc + t) * 256;
        int b = pxg >> 14, pxb = pxg & (HW - 1);
        const __nv_bfloat16* gin = in + ((size_t)b * ictot + icoff) * HW + pxb + wid * 32;

        #pragma unroll
        for (int pc = 0; pc < 3; pc++) {
            const __nv_bfloat16* src = gin + (size_t)pc * 16 * HW;
            uint32_t dstb = wInb + (uint32_t)pc * 1024u;
            #pragma unroll
            for (int i = 0; i < 2; i++) {
                int r = ldr + 8 * i;
                cp_async16(dstb + (uint32_t)(r * 64 + ldc * 16), src + (size_t)r * HW + ldc * 8);
            }
            CP_COMMIT();
        }

        float d[4][4][4];
        #pragma unroll
        for (int mi = 0; mi < 4; mi++)
            #pragma unroll
            for (int ni = 0; ni < 4; ni++)
                #pragma unroll
                for (int r = 0; r < 4; r++) d[mi][ni][r] = 0.f;

        for (int kc = 0; kc < NKC; kc++) {
            if (kc + 3 < NKC) {
                const __nv_bfloat16* src = gin + (size_t)(kc + 3) * 16 * HW;
                uint32_t dstb = wInb + (uint32_t)((kc + 3) & 3) * 1024u;
                #pragma unroll
                for (int i = 0; i < 2; i++) {
                    int r = ldr + 8 * i;
                    cp_async16(dstb + (uint32_t)(r * 64 + ldc * 16), src + (size_t)r * HW + ldc * 8);
                }
                CP_COMMIT();
                CP_WAIT3();
            } else if (kc + 2 < NKC) {
                CP_WAIT2();
            } else if (kc + 1 < NKC) {
                CP_WAIT1();
            } else {
                CP_WAIT0();
            }
            __syncwarp();

            uint32_t bufb = wInb + (uint32_t)(kc & 3) * 1024u;
            uint32_t bfr[2][4];
            ldmatrix_x4_trans(bfr[0], bufb + lmrow);
            ldmatrix_x4_trans(bfr[1], bufb + lmrow + 32);

            const uint4* wk = (const uint4*)(sm + kc * 2048);
            #pragma unroll
            for (int mi = 0; mi < 4; mi++) {
                uint4 av4 = wk[mi * 32 + lane];
                uint32_t a[4] = {av4.x, av4.y, av4.z, av4.w};
                mma_bf16(d[mi][0], a, bfr[0][0], bfr[0][1]);
                mma_bf16(d[mi][1], a, bfr[0][2], bfr[0][3]);
                mma_bf16(d[mi][2], a, bfr[1][0], bfr[1][1]);
                mma_bf16(d[mi][3], a, bfr[1][2], bfr[1][3]);
            }
        }

        #pragma unroll
        for (int mi = 0; mi < 4; mi++) {
            int oc0 = ocbase + mi * 16 + g;
            #pragma unroll
            for (int ni = 0; ni < 4; ni++) {
                int px0 = pxb + wid * 32 + ni * 8 + tig * 2;
                size_t o0 = ((size_t)b * octot + oc0) * HW + px0;
                size_t o2 = o0 + (size_t)8 * HW;
                float v0 = d[mi][ni][0], v1 = d[mi][ni][1];
                float v2 = d[mi][ni][2], v3 = d[mi][ni][3];
                if (outf) {
                    if (res) {
                        float2 e0 = *(const float2*)(res + o0);
                        float2 e2 = *(const float2*)(res + o2);
                        v0 += e0.x; v1 += e0.y; v2 += e2.x; v3 += e2.y;
                    }
                    *(float2*)(outf + o0) = make_float2(v0, v1);
                    *(float2*)(outf + o2) = make_float2(v2, v3);
                } else {
                    *(uint32_t*)(outb + o0) = bf16x2_pack(v0, v1);
                    *(uint32_t*)(outb + o2) = bf16x2_pack(v2, v3);
                }
            }
        }
    }
}

// ------- vectorized depthwise 3x3: 8 px/thread register window -----------------------
__global__ void __launch_bounds__(256) dwconv8_kernel(
        const __nv_bfloat16* __restrict__ in, const float* __restrict__ w, int C,
        __nv_bfloat16* __restrict__ out) {
    size_t base = ((size_t)blockIdx.x * 256 + threadIdx.x) * 8;
    int x0 = (int)(base & 127);
    int y  = (int)((base >> 7) & 127);
    size_t plane = base >> 14;
    int c = (int)(plane % C);
    const __nv_bfloat16* ip = in + (plane << 14);
    const float* wp = w + c * 9;
    float wr[9];
    #pragma unroll
    for (int i = 0; i < 9; i++) wr[i] = wp[i];

    float row[3][10];
    #pragma unroll
    for (int ky = 0; ky < 3; ky++) {
        int yy = y + ky - 1;
        if (yy >= 0 && yy <= 127) {
            const __nv_bfloat16* rp = ip + yy * 128;
            row[ky][0] = (x0 > 0) ? __bfloat162float(rp[x0 - 1]) : 0.f;
            uint4 m = *(const uint4*)(rp + x0);
            const __nv_bfloat16* mb = (const __nv_bfloat16*)&m;
            #pragma unroll
            for (int j = 0; j < 8; j++) row[ky][1 + j] = __bfloat162float(mb[j]);
            row[ky][9] = (x0 < 120) ? __bfloat162float(rp[x0 + 8]) : 0.f;
        } else {
            #pragma unroll
            for (int j = 0; j < 10; j++) row[ky][j] = 0.f;
        }
    }

    uint32_t pk[4];
    #pragma unroll
    for (int j = 0; j < 4; j++) {
        float a0 = 0.f, a1 = 0.f;
        #pragma unroll
        for (int ky = 0; ky < 3; ky++)
            #pragma unroll
            for (int kx = 0; kx < 3; kx++) {
                a0 += row[ky][2 * j + kx]     * wr[ky * 3 + kx];
                a1 += row[ky][2 * j + 1 + kx] * wr[ky * 3 + kx];
            }
        pk[j] = bf16x2_pack(a0, a1);
    }
    *(uint4*)(out + base) = *(uint4*)pk;
}

// ------- vectorized fused depthwise 3x3 (768ch pair) + gelu gate, 8 px/thread --------
__global__ void __launch_bounds__(256) dwconv_gelu8_kernel(
        const __nv_bfloat16* __restrict__ in, const float* __restrict__ w,
        __nv_bfloat16* __restrict__ out) {
    size_t base = ((size_t)blockIdx.x * 256 + threadIdx.x) * 8;   // out index space
    int x0 = (int)(base & 127);
    int y  = (int)((base >> 7) & 127);
    int pl = (int)(base >> 14);          // b*384 + c
    int c = pl % 384, b = pl / 384;
    const __nv_bfloat16* ip1 = in + ((size_t)b * 768 + c) * HW;
    const __nv_bfloat16* ip2 = ip1 + (size_t)384 * HW;
    const float* w1p = w + c * 9;
    const float* w2p = w + (c + 384) * 9;
    float w1[9], w2[9];
    #pragma unroll
    for (int i = 0; i < 9; i++) { w1[i] = w1p[i]; w2[i] = w2p[i]; }

    float r1[3][10], r2[3][10];
    #pragma unroll
    for (int ky = 0; ky < 3; ky++) {
        int yy = y + ky - 1;
        if (yy >= 0 && yy <= 127) {
            const __nv_bfloat16* a = ip1 + yy * 128;
            const __nv_bfloat16* bb = ip2 + yy * 128;
            r1[ky][0] = (x0 > 0) ? __bfloat162float(a[x0 - 1]) : 0.f;
            r2[ky][0] = (x0 > 0) ? __bfloat162float(bb[x0 - 1]) : 0.f;
            uint4 m1v = *(const uint4*)(a + x0);
            uint4 m2v = *(const uint4*)(bb + x0);
            const __nv_bfloat16* m1b = (const __nv_bfloat16*)&m1v;
            const __nv_bfloat16* m2b = (const __nv_bfloat16*)&m2v;
            #pragma unroll
            for (int j = 0; j < 8; j++) {
                r1[ky][1 + j] = __bfloat162float(m1b[j]);
                r2[ky][1 + j] = __bfloat162float(m2b[j]);
            }
            r1[ky][9] = (x0 < 120) ? __bfloat162float(a[x0 + 8]) : 0.f;
            r2[ky][9] = (x0 < 120) ? __bfloat162float(bb[x0 + 8]) : 0.f;
        } else {
            #pragma unroll
            for (int j = 0; j < 10; j++) { r1[ky][j] = 0.f; r2[ky][j] = 0.f; }
        }
    }

    uint32_t pk[4];
    #pragma unroll
    for (int j = 0; j < 4; j++) {
        float v[2];
        #pragma unroll
        for (int h = 0; h < 2; h++) {
            float a1 = 0.f, a2 = 0.f;
            #pragma unroll
            for (int ky = 0; ky < 3; ky++)
                #pragma unroll
                for (int kx = 0; kx < 3; kx++) {
                    a1 += r1[ky][2 * j + h + kx] * w1[ky * 3 + kx];
                    a2 += r2[ky][2 * j + h + kx] * w2[ky * 3 + kx];
                }
            float ge = 0.5f * a1 * (1.0f + erff(a1 * 0.70710678118654752f));
            v[h] = ge * a2;
        }
        pk[j] = bf16x2_pack(v[0], v[1]);
    }
    *(uint4*)(out + base) = *(uint4*)pk;
}

// ---------------- merged reciprocal-L2-norm for q and k rows, uint4 loads ------------
__global__ void rnorm2_kernel(const __nv_bfloat16* __restrict__ q,
                              const __nv_bfloat16* __restrict__ kvb,
                              float* __restrict__ rq, float* __restrict__ rk) {
    int row = blockIdx.x;                 // 0..767
    const __nv_bfloat16* p;
    float* rn;
    if (row < 384) {
        int b = row / 192, c = row % 192;
        p = q + ((size_t)b * 192 + c) * HW;
        rn = rq + row;
    } else {
        int r2 = row - 384;
        int b = r2 / 192, c = r2 % 192;
        p = kvb + ((size_t)b * 384 + c) * HW;
        rn = rk + r2;
    }
    float s = 0.f;
    for (int i = threadIdx.x * 8; i < HW; i += 2048) {
        uint4 m = *(const uint4*)(p + i);
        const __nv_bfloat16* mb = (const __nv_bfloat16*)&m;
        #pragma unroll
        for (int j = 0; j < 8; j++) { float v = __bfloat162float(mb[j]); s += v * v; }
    }
    __shared__ float red[8];
    #pragma unroll
    for (int o = 16; o; o >>= 1) s += __shfl_down_sync(0xffffffffu, s, o);
    if ((threadIdx.x & 31) == 0) red[threadIdx.x >> 5] = s;
    __syncthreads();
    if (threadIdx.x < 32) {
        s = (threadIdx.x < 8) ? red[threadIdx.x] : 0.f;
        #pragma unroll
        for (int o = 4; o; o >>= 1) s += __shfl_down_sync(0xffffffffu, s, o);
        if (threadIdx.x == 0) rn[0] = 1.0f / fmaxf(sqrtf(s), 1e-12f);
    }
}

// ---------------- q@k^T partials, bf16 in, 32 px-chunks of 512 ----------------------
__global__ void qk_kernel(const __nv_bfloat16* __restrict__ q,
                          const __nv_bfloat16* __restrict__ kv,
                          float* __restrict__ Sp) {
    int pc = blockIdx.x, hh = blockIdx.y, b = blockIdx.z;
    const __nv_bfloat16* qb = q  + ((size_t)b * 192 + hh * 32) * HW + pc * 512;
    const __nv_bfloat16* kb = kv + ((size_t)b * 384 + hh * 32) * HW + pc * 512;
    __shared__ float sq[32 * 33];
    __shared__ float sk[32 * 33];
    int t = threadIdx.x;
    int i = t & 31, jg = t >> 5;
    float acc[4] = {0.f, 0.f, 0.f, 0.f};
    for (int p0 = 0; p0 < 512; p0 += 32) {
        #pragma unroll
        for (int l = 0; l < 4; l++) {
            int idx = t + l * 256;
            int r = idx >> 5, cc = idx & 31;
            sq[r * 33 + cc] = __bfloat162float(qb[(size_t)r * HW + p0 + cc]);
            sk[r * 33 + cc] = __bfloat162float(kb[(size_t)r * HW + p0 + cc]);
        }
        __syncthreads();
        #pragma unroll
        for (int p = 0; p < 32; p++) {
            float a = sq[i * 33 + p];
            #pragma unroll
            for (int j = 0; j < 4; j++) acc[j] += a * sk[(jg * 4 + j) * 33 + p];
        }
        __syncthreads();
    }
    float* sp = Sp + (((size_t)(b * 6 + hh) * 32 + pc) * 1024);
    #pragma unroll
    for (int j = 0; j < 4; j++) sp[i * 32 + jg * 4 + j] = acc[j];
}

// ---------------- softmax (sums 32 partials) ------------------------------------------
__global__ void softmax_kernel(const float* __restrict__ Sp, const float* __restrict__ rq,
                               const float* __restrict__ rk, const float* __restrict__ temp,
                               float* __restrict__ attn) {
    int bh = blockIdx.x;
    int b = bh / 6, hh = bh % 6;
    int t = threadIdx.x;
    int i = t >> 5, j = t & 31;
    const float* sp = Sp + (size_t)bh * 32768 + i * 32 + j;
    float s = 0.f;
    #pragma unroll
    for (int pc = 0; pc < 32; pc++) s += sp[pc * 1024];
    s *= rq[b * 192 + hh * 32 + i] * rk[b * 192 + hh * 32 + j] * temp[hh];
    float mx = s;
    #pragma unroll
    for (int o = 16; o; o >>= 1) mx = fmaxf(mx, __shfl_xor_sync(0xffffffffu, mx, o));
    float e = expf(s - mx);
    float sum = e;
    #pragma unroll
    for (int o = 16; o; o >>= 1) sum += __shfl_xor_sync(0xffffffffu, sum, o);
    attn[(size_t)bh * 1024 + i * 32 + j] = e / sum;
}

// ---------------- out = attn @ v, bf16 ----------------------------------------------
__global__ void av_kernel(const float* __restrict__ attn,
                          const __nv_bfloat16* __restrict__ kv,
                          __nv_bfloat16* __restrict__ out) {
    int b = blockIdx.z, hh = blockIdx.y;
    int p = blockIdx.x * 256 + threadIdx.x;
    __shared__ float sA[1024];
    for (int l = threadIdx.x; l < 1024; l += 256)
        sA[l] = attn[(size_t)(b * 6 + hh) * 1024 + l];
    __syncthreads();
    const __nv_bfloat16* vb = kv + ((size_t)b * 384 + 192 + hh * 32) * HW + p;
    float v[32];
    #pragma unroll
    for (int e = 0; e < 32; e++) v[e] = __bfloat162float(vb[(size_t)e * HW]);
    __nv_bfloat16* ob = out + ((size_t)b * 192 + hh * 32) * HW + p;
    #pragma unroll
    for (int i = 0; i < 32; i++) {
        float acc = 0.f;
        #pragma unroll
        for (int e = 0; e < 32; e++) acc += sA[i * 32 + e] * v[e];
        ob[(size_t)i * HW] = __float2bfloat16(acc);
    }
}

// ====================================================================================
extern "C" void kernel_launch(void* const* d_in, const int* in_sizes, int n_in,
                              void* d_out, int out_size) {
    const float* x      = (const float*)d_in[0];
    const float* k_v    = (const float*)d_in[1];
    const float* ln1_w  = (const float*)d_in[2];
    const float* ln1_b  = (const float*)d_in[3];
    const float* temp   = (const float*)d_in[4];
    const float* w_kR   = (const float*)d_in[5];
    const float* w_kI   = (const float*)d_in[6];
    const float* w_qR   = (const float*)d_in[7];
    const float* w_qdw  = (const float*)d_in[8];
    const float* w_kvI  = (const float*)d_in[9];
    const float* w_kvdw = (const float*)d_in[10];
    const float* w_po   = (const float*)d_in[11];
    const float* ln2_w  = (const float*)d_in[12];
    const float* ln2_b  = (const float*)d_in[13];
    const float* w_ffk  = (const float*)d_in[14];
    const float* w_pin  = (const float*)d_in[15];
    const float* w_dw   = (const float*)d_in[16];
    const float* w_pout = (const float*)d_in[17];
    float* out = (float*)d_out;

    float* sc = nullptr;
    cudaGetSymbolAddress((void**)&sc, g_scratch);
    __nv_bfloat16* xs  = (__nv_bfloat16*)(sc + OFF_XS);
    __nv_bfloat16* t1  = (__nv_bfloat16*)(sc + OFF_T1);
    __nv_bfloat16* q   = (__nv_bfloat16*)(sc + OFF_Q);
    __nv_bfloat16* kvp = (__nv_bfloat16*)(sc + OFF_KVP);
    __nv_bfloat16* kvb = (__nv_bfloat16*)(sc + OFF_KVB);
    __nv_bfloat16* yp  = (__nv_bfloat16*)(sc + OFF_YP);
    float* m1  = sc + OFF_M1;
    float* mf  = sc + OFF_MF;
    float* rq  = sc + OFF_RQ;
    float* rk  = sc + OFF_RK;
    float* Sp  = sc + OFF_SP;
    float* att = sc + OFF_ATT;
    uint32_t* wq    = (uint32_t*)(sc + OFF_WQ);
    uint32_t* wkv   = (uint32_t*)(sc + OFF_WKV);
    uint32_t* wpo   = (uint32_t*)(sc + OFF_WPO);
    uint32_t* wpin  = (uint32_t*)(sc + OFF_WPIN);
    uint32_t* wpout = (uint32_t*)(sc + OFF_WPOUT);

    cudaFuncSetAttribute(conv_mma_kernel, cudaFuncAttributeMaxDynamicSharedMemorySize, 81920);
    auto smb = [](int NKC) { return (size_t)NKC * 2048 + 32768; };

    int tail = out_size - 6291456;
    if (tail < 0) tail = 0;
    if (tail > 512) tail = 512;

    // launches 1-3 (launch #4 = conv_q for ncu capture)
    prep_kernel<<<5, 256>>>(k_v, w_kR, w_kI, w_ffk, m1, mf, out + 6291456, tail);
    wpack_all_kernel<<<594, 256>>>(w_qR, w_kvI, w_po, w_pin, w_pout,
                                   wq, wkv, wpo, wpin, wpout);
    ln_scale_kernel<<<256, 512>>>(x, ln1_w, ln1_b, m1, xs);

    // attention branch
    conv_mma_kernel<<<dim3(128, 3), 256, smb(9)>>>(xs, 192, 0, 9, wq, 192, 1,
                                                   nullptr, nullptr, t1);
    conv_mma_kernel<<<dim3(128, 6), 256, smb(3)>>>(xs, 192, 144, 3, wkv, 384, 1,
                                                   nullptr, nullptr, kvp);
    dwconv8_kernel<<<(2 * 192 * HW) / 2048, 256>>>(t1, w_qdw, 192, q);
    dwconv8_kernel<<<(2 * 384 * HW) / 2048, 256>>>(kvp, w_kvdw, 384, kvb);
    rnorm2_kernel<<<768, 256>>>(q, kvb, rq, rk);
    qk_kernel<<<dim3(32, 6, 2), 256>>>(q, kvb, Sp);
    softmax_kernel<<<12, 1024>>>(Sp, rq, rk, temp, att);
    av_kernel<<<dim3(64, 6, 2), 256>>>(att, kvb, t1);
    conv_mma_kernel<<<dim3(128, 3), 256, smb(12)>>>(t1, 192, 0, 12, wpo, 192, 1,
                                                    x, out, nullptr);

    // GDFN feed-forward
    ln_scale_kernel<<<256, 512>>>(out, ln2_w, ln2_b, mf, xs);
    conv_mma_kernel<<<dim3(128, 12), 256, smb(12)>>>(xs, 192, 0, 12, wpin, 768, 1,
                                                     nullptr, nullptr, yp);
    dwconv_gelu8_kernel<<<(2 * 384 * HW) / 2048, 256>>>(yp, w_dw, kvp);
    conv_mma_kernel<<<dim3(128, 3), 256, smb(24)>>>(kvp, 384, 0, 24, wpout, 192, 1,
                                                    out, out, nullptr);
}